// round 1
// baseline (speedup 1.0000x reference)
#include <cuda_runtime.h>

#define SEQ    4096
#define DMODEL 512
#define NH     8
#define HD     64
#define KDIM   512
#define NW     (SEQ / 32)   // 128 mask words per row

// ---------------- scratch (device globals; no allocation allowed) ----------------
__device__ float    g_Q[SEQ * DMODEL];
__device__ float    g_K[SEQ * DMODEL];
__device__ float    g_V[SEQ * DMODEL];
__device__ float    g_C[SEQ * DMODEL];
__device__ unsigned g_mb[SEQ * NW];

// ---------------- mask pack: int32 [S,S] -> bitmask (2 MB, L2-resident) ----------------
__global__ void mask_pack_kernel(const int* __restrict__ mask)
{
    int gid = blockIdx.x * 256 + threadIdx.x;
    int v = mask[gid];
    unsigned b = __ballot_sync(0xffffffffu, v != 0);
    if ((threadIdx.x & 31) == 0) g_mb[gid >> 5] = b;
}

// ---------------- QKV projection: out = X @ W^T + b ----------------
// 128x128 tile, BK=16, 256 threads, 8x8 per thread (split-tile mapping -> conflict-free LDS.128)
__global__ __launch_bounds__(256) void qkv_gemm_kernel(
    const float* __restrict__ X,
    const float* __restrict__ Wq, const float* __restrict__ Bq,
    const float* __restrict__ Wk, const float* __restrict__ Bk,
    const float* __restrict__ Wv, const float* __restrict__ Bv)
{
    const float* W; const float* bias; float* out;
    if (blockIdx.z == 0)      { W = Wq; bias = Bq; out = g_Q; }
    else if (blockIdx.z == 1) { W = Wk; bias = Bk; out = g_K; }
    else                      { W = Wv; bias = Bv; out = g_V; }

    __shared__ float As[16][128];
    __shared__ float Bs[16][128];

    const int tid = threadIdx.x;
    const int tx = tid & 15, ty = tid >> 4;
    const int m0 = blockIdx.y * 128, n0 = blockIdx.x * 128;

    float acc[8][8];
    #pragma unroll
    for (int i = 0; i < 8; i++)
        #pragma unroll
        for (int j = 0; j < 8; j++) acc[i][j] = 0.0f;

    for (int k0 = 0; k0 < KDIM; k0 += 16) {
        #pragma unroll
        for (int l = 0; l < 2; l++) {
            int idx = tid + l * 256;       // 0..511
            int r   = idx >> 2;            // 0..127
            int c4  = (idx & 3) << 2;      // 0,4,8,12
            float4 va = *reinterpret_cast<const float4*>(X + (m0 + r) * KDIM + k0 + c4);
            As[c4 + 0][r] = va.x; As[c4 + 1][r] = va.y; As[c4 + 2][r] = va.z; As[c4 + 3][r] = va.w;
            float4 vb = *reinterpret_cast<const float4*>(W + (n0 + r) * KDIM + k0 + c4);
            Bs[c4 + 0][r] = vb.x; Bs[c4 + 1][r] = vb.y; Bs[c4 + 2][r] = vb.z; Bs[c4 + 3][r] = vb.w;
        }
        __syncthreads();
        #pragma unroll
        for (int kk = 0; kk < 16; kk++) {
            float a[8], b[8];
            float4 t;
            t = *reinterpret_cast<const float4*>(&As[kk][ty * 4]);        a[0] = t.x; a[1] = t.y; a[2] = t.z; a[3] = t.w;
            t = *reinterpret_cast<const float4*>(&As[kk][64 + ty * 4]);   a[4] = t.x; a[5] = t.y; a[6] = t.z; a[7] = t.w;
            t = *reinterpret_cast<const float4*>(&Bs[kk][tx * 4]);        b[0] = t.x; b[1] = t.y; b[2] = t.z; b[3] = t.w;
            t = *reinterpret_cast<const float4*>(&Bs[kk][64 + tx * 4]);   b[4] = t.x; b[5] = t.y; b[6] = t.z; b[7] = t.w;
            #pragma unroll
            for (int i = 0; i < 8; i++)
                #pragma unroll
                for (int j = 0; j < 8; j++)
                    acc[i][j] += a[i] * b[j];
        }
        __syncthreads();
    }

    #pragma unroll
    for (int i = 0; i < 8; i++) {
        int m = m0 + ((i < 4) ? (ty * 4 + i) : (64 + ty * 4 + i - 4));
        {
            int n = n0 + tx * 4;
            float4 o = { acc[i][0] + bias[n],     acc[i][1] + bias[n + 1],
                         acc[i][2] + bias[n + 2], acc[i][3] + bias[n + 3] };
            *reinterpret_cast<float4*>(out + m * DMODEL + n) = o;
        }
        {
            int n = n0 + 64 + tx * 4;
            float4 o = { acc[i][4] + bias[n],     acc[i][5] + bias[n + 1],
                         acc[i][6] + bias[n + 2], acc[i][7] + bias[n + 3] };
            *reinterpret_cast<float4*>(out + m * DMODEL + n) = o;
        }
    }
}

// ---------------- flash attention (per head, 128-row q tile, 64-col k tiles) ----------------
// Head h of Q/K/V is the contiguous slice g_X + h*SEQ*HD viewed as [SEQ][HD] (raw reshape!)
#define FLASH_SMEM_BYTES ((128 * 64 + 64 * 68 + 64 * 64 + 128 * 64 + 256) * 4)

__global__ __launch_bounds__(256, 2) void flash_attn_kernel()
{
    extern __shared__ float sm_[];
    float (*Qs)[HD]  = reinterpret_cast<float(*)[HD]>(sm_);                                // 128x64
    float (*Kst)[68] = reinterpret_cast<float(*)[68]>(sm_ + 128 * 64);                     // 64x68 [d][c]
    float (*Vs)[HD]  = reinterpret_cast<float(*)[HD]>(sm_ + 128 * 64 + 64 * 68);           // 64x64
    float (*Ps)[HD]  = reinterpret_cast<float(*)[HD]>(sm_ + 128 * 64 + 64 * 68 + 64 * 64); // 128x64
    unsigned* Ms     = reinterpret_cast<unsigned*>(sm_ + 128 * 64 + 64 * 68 + 64 * 64 + 128 * 64); // 128x2

    const int tid = threadIdx.x;
    const int tx = tid & 15, ty = tid >> 4;
    const int h  = blockIdx.y;
    const int q0 = blockIdx.x * 128;
    const float* Qg = g_Q + h * (SEQ * HD);
    const float* Kg = g_K + h * (SEQ * HD);
    const float* Vg = g_V + h * (SEQ * HD);

    // load Q tile (kept resident): 128x64 floats
    #pragma unroll
    for (int l = 0; l < 8; l++) {
        int idx = tid + l * 256;
        int r = idx >> 4, c4 = (idx & 15) << 2;
        *reinterpret_cast<float4*>(&Qs[r][c4]) =
            *reinterpret_cast<const float4*>(Qg + (q0 + r) * HD + c4);
    }

    float o[8][4];
    float m_i[8], l_i[8];
    #pragma unroll
    for (int i = 0; i < 8; i++) {
        m_i[i] = -1e30f; l_i[i] = 0.0f;
        #pragma unroll
        for (int j = 0; j < 4; j++) o[i][j] = 0.0f;
    }

    for (int kb = 0; kb < SEQ / 64; kb++) {
        const int k0 = kb * 64;
        // load K (transposed, padded) + V + mask tile
        #pragma unroll
        for (int l = 0; l < 4; l++) {
            int idx = tid + l * 256;           // 0..1023
            int c = idx >> 4, d4 = (idx & 15) << 2;
            float4 kv = *reinterpret_cast<const float4*>(Kg + (k0 + c) * HD + d4);
            Kst[d4 + 0][c] = kv.x; Kst[d4 + 1][c] = kv.y; Kst[d4 + 2][c] = kv.z; Kst[d4 + 3][c] = kv.w;
            *reinterpret_cast<float4*>(&Vs[c][d4]) =
                *reinterpret_cast<const float4*>(Vg + (k0 + c) * HD + d4);
        }
        {
            int r = tid >> 1, w = tid & 1;
            Ms[(r << 1) | w] = g_mb[(q0 + r) * NW + (kb << 1) + w];
        }
        __syncthreads();

        // S = Q K^T
        float s[8][4];
        #pragma unroll
        for (int i = 0; i < 8; i++)
            #pragma unroll
            for (int j = 0; j < 4; j++) s[i][j] = 0.0f;

        #pragma unroll
        for (int d0 = 0; d0 < HD; d0 += 4) {
            float kf[4][4];
            #pragma unroll
            for (int dd = 0; dd < 4; dd++) {
                float4 t = *reinterpret_cast<const float4*>(&Kst[d0 + dd][tx * 4]);
                kf[dd][0] = t.x; kf[dd][1] = t.y; kf[dd][2] = t.z; kf[dd][3] = t.w;
            }
            #pragma unroll
            for (int i = 0; i < 8; i++) {
                float4 q = *reinterpret_cast<const float4*>(&Qs[ty * 8 + i][d0]);
                #pragma unroll
                for (int j = 0; j < 4; j++)
                    s[i][j] += q.x * kf[0][j] + q.y * kf[1][j] + q.z * kf[2][j] + q.w * kf[3][j];
            }
        }

        // online softmax (row = ty*8+i, spread across 16 lanes; width-16 shuffles)
        #pragma unroll
        for (int i = 0; i < 8; i++) {
            unsigned mwv = Ms[((ty * 8 + i) << 1) + (tx >> 3)];
            float sv[4];
            #pragma unroll
            for (int j = 0; j < 4; j++) {
                float pen = ((mwv >> (((tx & 7) << 2) + j)) & 1u) ? -1e9f : 0.0f;
                sv[j] = fmaf(s[i][j], 0.125f, pen);
            }
            float mx = fmaxf(fmaxf(sv[0], sv[1]), fmaxf(sv[2], sv[3]));
            #pragma unroll
            for (int off = 8; off > 0; off >>= 1)
                mx = fmaxf(mx, __shfl_xor_sync(0xffffffffu, mx, off, 16));
            float mnew = fmaxf(m_i[i], mx);
            float corr = __expf(m_i[i] - mnew);
            float p[4]; float rs = 0.0f;
            #pragma unroll
            for (int j = 0; j < 4; j++) { p[j] = __expf(sv[j] - mnew); rs += p[j]; }
            #pragma unroll
            for (int off = 8; off > 0; off >>= 1)
                rs += __shfl_xor_sync(0xffffffffu, rs, off, 16);
            m_i[i] = mnew;
            l_i[i] = l_i[i] * corr + rs;
            #pragma unroll
            for (int j = 0; j < 4; j++) o[i][j] *= corr;
            float4 pw = { p[0], p[1], p[2], p[3] };
            *reinterpret_cast<float4*>(&Ps[ty * 8 + i][tx * 4]) = pw;
        }
        __syncthreads();

        // O += P @ V
        #pragma unroll
        for (int c0 = 0; c0 < 64; c0 += 4) {
            float vf[4][4];
            #pragma unroll
            for (int cc = 0; cc < 4; cc++) {
                float4 t = *reinterpret_cast<const float4*>(&Vs[c0 + cc][tx * 4]);
                vf[cc][0] = t.x; vf[cc][1] = t.y; vf[cc][2] = t.z; vf[cc][3] = t.w;
            }
            #pragma unroll
            for (int i = 0; i < 8; i++) {
                float4 pp = *reinterpret_cast<const float4*>(&Ps[ty * 8 + i][c0]);
                #pragma unroll
                for (int j = 0; j < 4; j++)
                    o[i][j] += pp.x * vf[0][j] + pp.y * vf[1][j] + pp.z * vf[2][j] + pp.w * vf[3][j];
            }
        }
        __syncthreads();
    }

    float* Og = g_C + h * (SEQ * HD);
    #pragma unroll
    for (int i = 0; i < 8; i++) {
        float inv = 1.0f / l_i[i];
        float4 w = { o[i][0] * inv, o[i][1] * inv, o[i][2] * inv, o[i][3] * inv };
        *reinterpret_cast<float4*>(Og + (q0 + ty * 8 + i) * HD + tx * 4) = w;
    }
}

// ---------------- dense: out = merge_heads(Ctx) @ W^T + b ----------------
// merge fold: A[m][d] = g_C[(d>>6)*SEQ*HD + m*HD + (d&63)]
__global__ __launch_bounds__(256) void dense_gemm_kernel(
    float* __restrict__ out,
    const float* __restrict__ W, const float* __restrict__ bias)
{
    __shared__ float As[16][128];
    __shared__ float Bs[16][128];

    const int tid = threadIdx.x;
    const int tx = tid & 15, ty = tid >> 4;
    const int m0 = blockIdx.y * 128, n0 = blockIdx.x * 128;

    float acc[8][8];
    #pragma unroll
    for (int i = 0; i < 8; i++)
        #pragma unroll
        for (int j = 0; j < 8; j++) acc[i][j] = 0.0f;

    for (int k0 = 0; k0 < DMODEL; k0 += 16) {
        #pragma unroll
        for (int l = 0; l < 2; l++) {
            int idx = tid + l * 256;
            int r   = idx >> 2;
            int c4  = (idx & 3) << 2;
            int kd  = k0 + c4;
            float4 va = *reinterpret_cast<const float4*>(
                g_C + (kd >> 6) * (SEQ * HD) + (m0 + r) * HD + (kd & 63));
            As[c4 + 0][r] = va.x; As[c4 + 1][r] = va.y; As[c4 + 2][r] = va.z; As[c4 + 3][r] = va.w;
            float4 vb = *reinterpret_cast<const float4*>(W + (n0 + r) * DMODEL + k0 + c4);
            Bs[c4 + 0][r] = vb.x; Bs[c4 + 1][r] = vb.y; Bs[c4 + 2][r] = vb.z; Bs[c4 + 3][r] = vb.w;
        }
        __syncthreads();
        #pragma unroll
        for (int kk = 0; kk < 16; kk++) {
            float a[8], b[8];
            float4 t;
            t = *reinterpret_cast<const float4*>(&As[kk][ty * 4]);        a[0] = t.x; a[1] = t.y; a[2] = t.z; a[3] = t.w;
            t = *reinterpret_cast<const float4*>(&As[kk][64 + ty * 4]);   a[4] = t.x; a[5] = t.y; a[6] = t.z; a[7] = t.w;
            t = *reinterpret_cast<const float4*>(&Bs[kk][tx * 4]);        b[0] = t.x; b[1] = t.y; b[2] = t.z; b[3] = t.w;
            t = *reinterpret_cast<const float4*>(&Bs[kk][64 + tx * 4]);   b[4] = t.x; b[5] = t.y; b[6] = t.z; b[7] = t.w;
            #pragma unroll
            for (int i = 0; i < 8; i++)
                #pragma unroll
                for (int j = 0; j < 8; j++)
                    acc[i][j] += a[i] * b[j];
        }
        __syncthreads();
    }

    #pragma unroll
    for (int i = 0; i < 8; i++) {
        int m = m0 + ((i < 4) ? (ty * 4 + i) : (64 + ty * 4 + i - 4));
        {
            int n = n0 + tx * 4;
            float4 o = { acc[i][0] + bias[n],     acc[i][1] + bias[n + 1],
                         acc[i][2] + bias[n + 2], acc[i][3] + bias[n + 3] };
            *reinterpret_cast<float4*>(out + m * DMODEL + n) = o;
        }
        {
            int n = n0 + 64 + tx * 4;
            float4 o = { acc[i][4] + bias[n],     acc[i][5] + bias[n + 1],
                         acc[i][6] + bias[n + 2], acc[i][7] + bias[n + 3] };
            *reinterpret_cast<float4*>(out + m * DMODEL + n) = o;
        }
    }
}

// ---------------- launch ----------------
extern "C" void kernel_launch(void* const* d_in, const int* in_sizes, int n_in,
                              void* d_out, int out_size)
{
    (void)in_sizes; (void)n_in; (void)out_size;
    const float* x  = (const float*)d_in[0];
    const int*   mk = (const int*)d_in[1];
    const float* wq = (const float*)d_in[2];
    const float* bq = (const float*)d_in[3];
    const float* wk = (const float*)d_in[4];
    const float* bk = (const float*)d_in[5];
    const float* wv = (const float*)d_in[6];
    const float* bv = (const float*)d_in[7];
    const float* dw = (const float*)d_in[8];
    const float* db = (const float*)d_in[9];
    float* out = (float*)d_out;

    cudaFuncSetAttribute(flash_attn_kernel,
                         cudaFuncAttributeMaxDynamicSharedMemorySize, FLASH_SMEM_BYTES);

    qkv_gemm_kernel<<<dim3(DMODEL / 128, SEQ / 128, 3), 256>>>(x, wq, bq, wk, bk, wv, bv);
    mask_pack_kernel<<<(SEQ * SEQ) / 256, 256>>>(mk);
    flash_attn_kernel<<<dim3(SEQ / 128, NH), 256, FLASH_SMEM_BYTES>>>();
    dense_gemm_kernel<<<dim3(DMODEL / 128, SEQ / 128), 256>>>(out, dw, db);
}

// round 5
// speedup vs baseline: 2.4319x; 2.4319x over previous
#include <cuda_runtime.h>
#include <cuda_fp16.h>
#include <cstdint>

#define SEQ    4096
#define DMODEL 512
#define NH     8
#define HD     64
#define KDIM   512
#define NW     (SEQ / 32)   // 128 mask words per row

#define BM 128
#define BN 64
#define NKB (SEQ / BN)

// ---------------- scratch (device globals; no allocation allowed) ----------------
__device__ __half   g_Qh[SEQ * DMODEL];
__device__ __half   g_Kh[SEQ * DMODEL];
__device__ __half   g_Vh[SEQ * DMODEL];
__device__ float    g_C[SEQ * DMODEL];
__device__ unsigned g_mb[SEQ * NW];

// ================= helpers =================
__device__ __forceinline__ uint32_t smem_u32(const void* p) {
    uint32_t a;
    asm("{ .reg .u64 t; cvta.to.shared.u64 t, %1; cvt.u32.u64 %0, t; }" : "=r"(a) : "l"(p));
    return a;
}
__device__ __forceinline__ void cp16(uint32_t dst, const void* src) {
    asm volatile("cp.async.cg.shared.global [%0], [%1], 16;" :: "r"(dst), "l"(src));
}
__device__ __forceinline__ void cp_commit() { asm volatile("cp.async.commit_group;"); }
__device__ __forceinline__ void cp_wait0()  { asm volatile("cp.async.wait_group 0;" ::: "memory"); }

__device__ __forceinline__ void ldsm4(uint32_t* r, uint32_t addr) {
    asm volatile("ldmatrix.sync.aligned.m8n8.x4.shared.b16 {%0,%1,%2,%3}, [%4];"
        : "=r"(r[0]), "=r"(r[1]), "=r"(r[2]), "=r"(r[3]) : "r"(addr));
}
__device__ __forceinline__ void ldsm4t(uint32_t* r, uint32_t addr) {
    asm volatile("ldmatrix.sync.aligned.m8n8.x4.trans.shared.b16 {%0,%1,%2,%3}, [%4];"
        : "=r"(r[0]), "=r"(r[1]), "=r"(r[2]), "=r"(r[3]) : "r"(addr));
}
// D = A*B + D   (m16n8k16, f16 in, f32 accum)
__device__ __forceinline__ void mma16816(float* d, const uint32_t* a, const uint32_t* b) {
    asm volatile("mma.sync.aligned.m16n8k16.row.col.f32.f16.f16.f32 "
        "{%0,%1,%2,%3}, {%4,%5,%6,%7}, {%8,%9}, {%0,%1,%2,%3};"
        : "+f"(d[0]), "+f"(d[1]), "+f"(d[2]), "+f"(d[3])
        : "r"(a[0]), "r"(a[1]), "r"(a[2]), "r"(a[3]), "r"(b[0]), "r"(b[1]));
}
__device__ __forceinline__ uint32_t pack_h2(float a, float b) {
    __half2 h = __floats2half2_rn(a, b);   // x(lo)=a, y(hi)=b
    return *reinterpret_cast<uint32_t*>(&h);
}
// exp(s * 0.125) via exp2 FFMA polynomial (MUFU rt=8 too slow at this volume)
__device__ __forceinline__ float fexp8(float s) {
    const float C = 0.125f * 1.4426950408889634f;
    float z = fmaf(s, C, 12582912.0f);          // 1.5*2^23 magic round
    float n = z - 12582912.0f;
    float r = fmaf(s, C, -n);                   // r in [-0.5, 0.5]
    float p = 1.3333558146e-3f;
    p = fmaf(p, r, 9.6181291076e-3f);
    p = fmaf(p, r, 5.5504108665e-2f);
    p = fmaf(p, r, 2.4022650696e-1f);
    p = fmaf(p, r, 6.9314718056e-1f);
    p = fmaf(p, r, 1.0f);
    return __int_as_float(__float_as_int(p) + (__float_as_int(z) << 23));
}

// ---------------- mask pack: int32 [S,S] -> bitmask (2 MB, L2-resident) ----------------
__global__ void mask_pack_kernel(const int* __restrict__ mask)
{
    int gid = blockIdx.x * 256 + threadIdx.x;
    int v = mask[gid];
    unsigned b = __ballot_sync(0xffffffffu, v != 0);
    if ((threadIdx.x & 31) == 0) g_mb[gid >> 5] = b;
}

// ---------------- QKV projection: out = X @ W^T + b  (fp32 SIMT, fp16 output) ----------------
__global__ __launch_bounds__(256) void qkv_gemm_kernel(
    const float* __restrict__ X,
    const float* __restrict__ Wq, const float* __restrict__ Bq,
    const float* __restrict__ Wk, const float* __restrict__ Bk,
    const float* __restrict__ Wv, const float* __restrict__ Bv)
{
    const float* W; const float* bias; __half* out;
    if (blockIdx.z == 0)      { W = Wq; bias = Bq; out = g_Qh; }
    else if (blockIdx.z == 1) { W = Wk; bias = Bk; out = g_Kh; }
    else                      { W = Wv; bias = Bv; out = g_Vh; }

    __shared__ float As[16][128];
    __shared__ float Bs[16][128];

    const int tid = threadIdx.x;
    const int tx = tid & 15, ty = tid >> 4;
    const int m0 = blockIdx.y * 128, n0 = blockIdx.x * 128;

    float acc[8][8];
    #pragma unroll
    for (int i = 0; i < 8; i++)
        #pragma unroll
        for (int j = 0; j < 8; j++) acc[i][j] = 0.0f;

    for (int k0 = 0; k0 < KDIM; k0 += 16) {
        #pragma unroll
        for (int l = 0; l < 2; l++) {
            int idx = tid + l * 256;
            int r   = idx >> 2;
            int c4  = (idx & 3) << 2;
            float4 va = *reinterpret_cast<const float4*>(X + (m0 + r) * KDIM + k0 + c4);
            As[c4 + 0][r] = va.x; As[c4 + 1][r] = va.y; As[c4 + 2][r] = va.z; As[c4 + 3][r] = va.w;
            float4 vb = *reinterpret_cast<const float4*>(W + (n0 + r) * KDIM + k0 + c4);
            Bs[c4 + 0][r] = vb.x; Bs[c4 + 1][r] = vb.y; Bs[c4 + 2][r] = vb.z; Bs[c4 + 3][r] = vb.w;
        }
        __syncthreads();
        #pragma unroll
        for (int kk = 0; kk < 16; kk++) {
            float a[8], b[8];
            float4 t;
            t = *reinterpret_cast<const float4*>(&As[kk][ty * 4]);      a[0]=t.x; a[1]=t.y; a[2]=t.z; a[3]=t.w;
            t = *reinterpret_cast<const float4*>(&As[kk][64 + ty * 4]); a[4]=t.x; a[5]=t.y; a[6]=t.z; a[7]=t.w;
            t = *reinterpret_cast<const float4*>(&Bs[kk][tx * 4]);      b[0]=t.x; b[1]=t.y; b[2]=t.z; b[3]=t.w;
            t = *reinterpret_cast<const float4*>(&Bs[kk][64 + tx * 4]); b[4]=t.x; b[5]=t.y; b[6]=t.z; b[7]=t.w;
            #pragma unroll
            for (int i = 0; i < 8; i++)
                #pragma unroll
                for (int j = 0; j < 8; j++)
                    acc[i][j] += a[i] * b[j];
        }
        __syncthreads();
    }

    #pragma unroll
    for (int i = 0; i < 8; i++) {
        int m = m0 + ((i < 4) ? (ty * 4 + i) : (64 + ty * 4 + i - 4));
        {
            int n = n0 + tx * 4;
            uint2 u = { pack_h2(acc[i][0] + bias[n],     acc[i][1] + bias[n + 1]),
                        pack_h2(acc[i][2] + bias[n + 2], acc[i][3] + bias[n + 3]) };
            *reinterpret_cast<uint2*>(out + m * DMODEL + n) = u;
        }
        {
            int n = n0 + 64 + tx * 4;
            uint2 u = { pack_h2(acc[i][4] + bias[n],     acc[i][5] + bias[n + 1]),
                        pack_h2(acc[i][6] + bias[n + 2], acc[i][7] + bias[n + 3]) };
            *reinterpret_cast<uint2*>(out + m * DMODEL + n) = u;
        }
    }
}

// ---------------- fp16 mma.sync flash attention ----------------
// SMEM: fp16 tiles, rows padded to 72 halves (144 B) -> conflict-free ldmatrix
#define QPITCH 144
#define OFF_Q   0
#define OFF_K0  (128 * QPITCH)                 // 18432
#define OFF_K1  (OFF_K0 + 64 * QPITCH)
#define OFF_V0  (OFF_K1 + 64 * QPITCH)
#define OFF_V1  (OFF_V0 + 64 * QPITCH)
#define FL_SMEM (OFF_V1 + 64 * QPITCH)         // 92160 B... (128+4*64)*144 = 55296 B

__global__ void __launch_bounds__(256, 1) flash_mma_kernel()
{
    extern __shared__ __align__(128) char smem[];
    const uint32_t sb = smem_u32(smem);
    const int tid  = threadIdx.x;
    const int wid  = tid >> 5;
    const int lane = tid & 31;
    const int h    = blockIdx.y;
    const int q0   = blockIdx.x * BM;
    const __half* Qg = g_Qh + h * (SEQ * HD);
    const __half* Kg = g_Kh + h * (SEQ * HD);
    const __half* Vg = g_Vh + h * (SEQ * HD);

    // ---- prologue: Q -> smem (padded), K0/V0 via cp.async ----
    {
        int r = tid >> 1, c0 = (tid & 1) * 32;    // 32 halves each
        const uint4* src = reinterpret_cast<const uint4*>(Qg + (q0 + r) * HD + c0);
        char* dst = smem + OFF_Q + r * QPITCH + c0 * 2;
        #pragma unroll
        for (int k = 0; k < 4; k++)
            reinterpret_cast<uint4*>(dst)[k] = src[k];
    }
    #pragma unroll
    for (int l = 0; l < 2; l++) {
        int idx = tid + l * 256;                  // 0..511
        int r = idx >> 3, ch = (idx & 7) << 3;    // row, 8-half chunk
        cp16(sb + OFF_K0 + r * QPITCH + ch * 2, Kg + r * HD + ch);
        cp16(sb + OFF_V0 + r * QPITCH + ch * 2, Vg + r * HD + ch);
    }
    cp_commit();
    cp_wait0();
    __syncthreads();

    // lane-dependent ldmatrix address offsets
    const int qb = wid * 16;
    const uint32_t abase = ((((lane >> 3) & 1) * 8 + (lane & 7)) * QPITCH) + (((lane >> 4) & 1) * 16); // A & V-trans form
    const uint32_t kbase = ((((lane >> 4) & 1) * 8 + (lane & 7)) * QPITCH) + (((lane >> 3) & 1) * 16); // K (non-trans) form

    // Q A-fragments (persistent)
    uint32_t Aq[4][4];
    #pragma unroll
    for (int t = 0; t < 4; t++)
        ldsm4(Aq[t], sb + OFF_Q + qb * QPITCH + t * 32 + abase);

    float Oacc[8][4];
    #pragma unroll
    for (int j = 0; j < 8; j++)
        #pragma unroll
        for (int e = 0; e < 4; e++) Oacc[j][e] = 0.0f;

    const int row0 = q0 + qb + (lane >> 2);
    const int row1 = row0 + 8;
    const int qv = lane & 3;
    float lsum0 = 0.0f, lsum1 = 0.0f;

    for (int i = 0; i < NKB; i++) {
        const uint32_t kcur = sb + ((i & 1) ? OFF_K1 : OFF_K0);
        const uint32_t vcur = sb + ((i & 1) ? OFF_V1 : OFF_V0);

        // prefetch next K/V
        if (i + 1 < NKB) {
            const uint32_t kn = sb + ((i & 1) ? OFF_K0 : OFF_K1);
            const uint32_t vn = sb + ((i & 1) ? OFF_V0 : OFF_V1);
            const __half* Kn = Kg + (i + 1) * BN * HD;
            const __half* Vn = Vg + (i + 1) * BN * HD;
            #pragma unroll
            for (int l = 0; l < 2; l++) {
                int idx = tid + l * 256;
                int r = idx >> 3, ch = (idx & 7) << 3;
                cp16(kn + r * QPITCH + ch * 2, Kn + r * HD + ch);
                cp16(vn + r * QPITCH + ch * 2, Vn + r * HD + ch);
            }
            cp_commit();
        }

        uint2 m0 = *reinterpret_cast<const uint2*>(g_mb + row0 * NW + (i << 1));
        uint2 m1 = *reinterpret_cast<const uint2*>(g_mb + row1 * NW + (i << 1));

        // ---- S = Q K^T ----
        float S[8][4];
        #pragma unroll
        for (int j = 0; j < 8; j++)
            #pragma unroll
            for (int e = 0; e < 4; e++) S[j][e] = 0.0f;

        #pragma unroll
        for (int jp = 0; jp < 4; jp++) {
            #pragma unroll
            for (int t = 0; t < 4; t++) {
                uint32_t B[4];
                ldsm4(B, kcur + jp * (16 * QPITCH) + t * 32 + kbase);
                mma16816(S[2 * jp],     Aq[t], B);
                mma16816(S[2 * jp + 1], Aq[t], B + 2);
            }
        }

        // ---- softmax (no max-shift; masked -> exact 0) + pack P A-frags ----
        uint32_t Ap[4][4];
        #pragma unroll
        for (int j = 0; j < 8; j++) {
            unsigned w0 = (j < 4) ? m0.x : m0.y;
            unsigned w1 = (j < 4) ? m1.x : m1.y;
            int p0 = ((j & 3) << 3) + (qv << 1);
            float e0 = ((w0 >> p0) & 1u)       ? 0.0f : fexp8(S[j][0]);
            float e1 = ((w0 >> (p0 + 1)) & 1u) ? 0.0f : fexp8(S[j][1]);
            float e2 = ((w1 >> p0) & 1u)       ? 0.0f : fexp8(S[j][2]);
            float e3 = ((w1 >> (p0 + 1)) & 1u) ? 0.0f : fexp8(S[j][3]);
            lsum0 += e0 + e1;
            lsum1 += e2 + e3;
            int t = j >> 1;
            if ((j & 1) == 0) { Ap[t][0] = pack_h2(e0, e1); Ap[t][1] = pack_h2(e2, e3); }
            else              { Ap[t][2] = pack_h2(e0, e1); Ap[t][3] = pack_h2(e2, e3); }
        }

        // ---- O += P V ----
        #pragma unroll
        for (int jp = 0; jp < 4; jp++) {
            #pragma unroll
            for (int t = 0; t < 4; t++) {
                uint32_t B[4];
                ldsm4t(B, vcur + t * (16 * QPITCH) + jp * 32 + abase);
                mma16816(Oacc[2 * jp],     Ap[t], B);
                mma16816(Oacc[2 * jp + 1], Ap[t], B + 2);
            }
        }

        if (i + 1 < NKB) cp_wait0();
        __syncthreads();
    }

    // ---- epilogue: reduce row sums across quad, normalize, store ----
    lsum0 += __shfl_xor_sync(0xffffffffu, lsum0, 1);
    lsum0 += __shfl_xor_sync(0xffffffffu, lsum0, 2);
    lsum1 += __shfl_xor_sync(0xffffffffu, lsum1, 1);
    lsum1 += __shfl_xor_sync(0xffffffffu, lsum1, 2);
    float inv0 = 1.0f / lsum0;
    float inv1 = 1.0f / lsum1;

    float* C0 = g_C + h * (SEQ * HD) + row0 * HD;
    float* C1 = g_C + h * (SEQ * HD) + row1 * HD;
    #pragma unroll
    for (int j = 0; j < 8; j++) {
        int c = 8 * j + (qv << 1);
        float2 a = { Oacc[j][0] * inv0, Oacc[j][1] * inv0 };
        float2 b = { Oacc[j][2] * inv1, Oacc[j][3] * inv1 };
        *reinterpret_cast<float2*>(C0 + c) = a;
        *reinterpret_cast<float2*>(C1 + c) = b;
    }
}

// ---------------- dense: out = merge_heads(Ctx) @ W^T + b ----------------
__global__ __launch_bounds__(256) void dense_gemm_kernel(
    float* __restrict__ out,
    const float* __restrict__ W, const float* __restrict__ bias)
{
    __shared__ float As[16][128];
    __shared__ float Bs[16][128];

    const int tid = threadIdx.x;
    const int tx = tid & 15, ty = tid >> 4;
    const int m0 = blockIdx.y * 128, n0 = blockIdx.x * 128;

    float acc[8][8];
    #pragma unroll
    for (int i = 0; i < 8; i++)
        #pragma unroll
        for (int j = 0; j < 8; j++) acc[i][j] = 0.0f;

    for (int k0 = 0; k0 < DMODEL; k0 += 16) {
        #pragma unroll
        for (int l = 0; l < 2; l++) {
            int idx = tid + l * 256;
            int r   = idx >> 2;
            int c4  = (idx & 3) << 2;
            int kd  = k0 + c4;
            float4 va = *reinterpret_cast<const float4*>(
                g_C + (kd >> 6) * (SEQ * HD) + (m0 + r) * HD + (kd & 63));
            As[c4 + 0][r] = va.x; As[c4 + 1][r] = va.y; As[c4 + 2][r] = va.z; As[c4 + 3][r] = va.w;
            float4 vb = *reinterpret_cast<const float4*>(W + (n0 + r) * DMODEL + k0 + c4);
            Bs[c4 + 0][r] = vb.x; Bs[c4 + 1][r] = vb.y; Bs[c4 + 2][r] = vb.z; Bs[c4 + 3][r] = vb.w;
        }
        __syncthreads();
        #pragma unroll
        for (int kk = 0; kk < 16; kk++) {
            float a[8], b[8];
            float4 t;
            t = *reinterpret_cast<const float4*>(&As[kk][ty * 4]);      a[0]=t.x; a[1]=t.y; a[2]=t.z; a[3]=t.w;
            t = *reinterpret_cast<const float4*>(&As[kk][64 + ty * 4]); a[4]=t.x; a[5]=t.y; a[6]=t.z; a[7]=t.w;
            t = *reinterpret_cast<const float4*>(&Bs[kk][tx * 4]);      b[0]=t.x; b[1]=t.y; b[2]=t.z; b[3]=t.w;
            t = *reinterpret_cast<const float4*>(&Bs[kk][64 + tx * 4]); b[4]=t.x; b[5]=t.y; b[6]=t.z; b[7]=t.w;
            #pragma unroll
            for (int i = 0; i < 8; i++)
                #pragma unroll
                for (int j = 0; j < 8; j++)
                    acc[i][j] += a[i] * b[j];
        }
        __syncthreads();
    }

    #pragma unroll
    for (int i = 0; i < 8; i++) {
        int m = m0 + ((i < 4) ? (ty * 4 + i) : (64 + ty * 4 + i - 4));
        {
            int n = n0 + tx * 4;
            float4 o = { acc[i][0] + bias[n],     acc[i][1] + bias[n + 1],
                         acc[i][2] + bias[n + 2], acc[i][3] + bias[n + 3] };
            *reinterpret_cast<float4*>(out + m * DMODEL + n) = o;
        }
        {
            int n = n0 + 64 + tx * 4;
            float4 o = { acc[i][4] + bias[n],     acc[i][5] + bias[n + 1],
                         acc[i][6] + bias[n + 2], acc[i][7] + bias[n + 3] };
            *reinterpret_cast<float4*>(out + m * DMODEL + n) = o;
        }
    }
}

// ---------------- launch ----------------
extern "C" void kernel_launch(void* const* d_in, const int* in_sizes, int n_in,
                              void* d_out, int out_size)
{
    (void)in_sizes; (void)n_in; (void)out_size;
    const float* x  = (const float*)d_in[0];
    const int*   mk = (const int*)d_in[1];
    const float* wq = (const float*)d_in[2];
    const float* bq = (const float*)d_in[3];
    const float* wk = (const float*)d_in[4];
    const float* bk = (const float*)d_in[5];
    const float* wv = (const float*)d_in[6];
    const float* bv = (const float*)d_in[7];
    const float* dw = (const float*)d_in[8];
    const float* db = (const float*)d_in[9];
    float* out = (float*)d_out;

    cudaFuncSetAttribute(flash_mma_kernel,
                         cudaFuncAttributeMaxDynamicSharedMemorySize, FL_SMEM);

    qkv_gemm_kernel<<<dim3(DMODEL / 128, SEQ / 128, 3), 256>>>(x, wq, bq, wk, bk, wv, bv);
    mask_pack_kernel<<<(SEQ * SEQ) / 256, 256>>>(mk);
    flash_mma_kernel<<<dim3(SEQ / BM, NH), 256, FL_SMEM>>>();
    dense_gemm_kernel<<<dim3(DMODEL / 128, SEQ / 128), 256>>>(out, dw, db);
}

// round 6
// speedup vs baseline: 3.5096x; 1.4432x over previous
#include <cuda_runtime.h>
#include <cuda_fp16.h>
#include <cstdint>

#define SEQ    4096
#define DMODEL 512
#define NH     8
#define HD     64
#define KDIM   512
#define NW     (SEQ / 32)   // 128 mask words per row

#define BM 128
#define BN 64
#define NKB (SEQ / BN)

// ---------------- scratch (device globals; no allocation allowed) ----------------
__device__ __half   g_Xh[SEQ * KDIM];          // fp16 copy of x
__device__ __half   g_Wh[4 * DMODEL * KDIM];   // wq, wk, wv, dense (fp16)
__device__ __half   g_Qh[SEQ * DMODEL];
__device__ __half   g_Kh[SEQ * DMODEL];
__device__ __half   g_Vh[SEQ * DMODEL];
__device__ __half   g_Ch[SEQ * DMODEL];        // context (head-major), fp16
__device__ unsigned g_mb[SEQ * NW];

// ================= helpers =================
__device__ __forceinline__ uint32_t smem_u32(const void* p) {
    uint32_t a;
    asm("{ .reg .u64 t; cvta.to.shared.u64 t, %1; cvt.u32.u64 %0, t; }" : "=r"(a) : "l"(p));
    return a;
}
__device__ __forceinline__ void cp16(uint32_t dst, const void* src) {
    asm volatile("cp.async.cg.shared.global [%0], [%1], 16;" :: "r"(dst), "l"(src));
}
__device__ __forceinline__ void cp_commit() { asm volatile("cp.async.commit_group;"); }
__device__ __forceinline__ void cp_wait0()  { asm volatile("cp.async.wait_group 0;" ::: "memory"); }
__device__ __forceinline__ void cp_wait1()  { asm volatile("cp.async.wait_group 1;" ::: "memory"); }

__device__ __forceinline__ void ldsm4(uint32_t* r, uint32_t addr) {
    asm volatile("ldmatrix.sync.aligned.m8n8.x4.shared.b16 {%0,%1,%2,%3}, [%4];"
        : "=r"(r[0]), "=r"(r[1]), "=r"(r[2]), "=r"(r[3]) : "r"(addr));
}
__device__ __forceinline__ void ldsm4t(uint32_t* r, uint32_t addr) {
    asm volatile("ldmatrix.sync.aligned.m8n8.x4.trans.shared.b16 {%0,%1,%2,%3}, [%4];"
        : "=r"(r[0]), "=r"(r[1]), "=r"(r[2]), "=r"(r[3]) : "r"(addr));
}
// D = A*B + D   (m16n8k16, f16 in, f32 accum)
__device__ __forceinline__ void mma16816(float* d, const uint32_t* a, const uint32_t* b) {
    asm volatile("mma.sync.aligned.m16n8k16.row.col.f32.f16.f16.f32 "
        "{%0,%1,%2,%3}, {%4,%5,%6,%7}, {%8,%9}, {%0,%1,%2,%3};"
        : "+f"(d[0]), "+f"(d[1]), "+f"(d[2]), "+f"(d[3])
        : "r"(a[0]), "r"(a[1]), "r"(a[2]), "r"(a[3]), "r"(b[0]), "r"(b[1]));
}
__device__ __forceinline__ uint32_t pack_h2(float a, float b) {
    __half2 h = __floats2half2_rn(a, b);
    return *reinterpret_cast<uint32_t*>(&h);
}
// exp(s * 0.125) via exp2 FFMA polynomial
__device__ __forceinline__ float fexp8(float s) {
    const float C = 0.125f * 1.4426950408889634f;
    float z = fmaf(s, C, 12582912.0f);
    float n = z - 12582912.0f;
    float r = fmaf(s, C, -n);
    float p = 1.3333558146e-3f;
    p = fmaf(p, r, 9.6181291076e-3f);
    p = fmaf(p, r, 5.5504108665e-2f);
    p = fmaf(p, r, 2.4022650696e-1f);
    p = fmaf(p, r, 6.9314718056e-1f);
    p = fmaf(p, r, 1.0f);
    return __int_as_float(__float_as_int(p) + (__float_as_int(z) << 23));
}

// ---------------- convert: x + 4 weight matrices -> fp16 ----------------
__global__ __launch_bounds__(256) void convert_kernel(
    const float* __restrict__ x,  const float* __restrict__ wq,
    const float* __restrict__ wk, const float* __restrict__ wv,
    const float* __restrict__ dw)
{
    int f4 = blockIdx.x * 256 + threadIdx.x;   // 0 .. 786431
    const float4* src; __half* dst; int off;
    if (f4 < 524288) { src = (const float4*)x; off = f4; dst = g_Xh; }
    else {
        int t = f4 - 524288;
        int w = t >> 16; off = t & 65535;
        src = (const float4*)(w == 0 ? wq : w == 1 ? wk : w == 2 ? wv : dw);
        dst = g_Wh + w * (DMODEL * KDIM);
    }
    float4 v = src[off];
    uint2 u = { pack_h2(v.x, v.y), pack_h2(v.z, v.w) };
    *reinterpret_cast<uint2*>(dst + off * 4) = u;
}

// ---------------- mask pack: int32 [S,S] -> bitmask ----------------
__global__ void mask_pack_kernel(const int* __restrict__ mask)
{
    int gid = blockIdx.x * 256 + threadIdx.x;
    int v = mask[gid];
    unsigned b = __ballot_sync(0xffffffffu, v != 0);
    if ((threadIdx.x & 31) == 0) g_mb[gid >> 5] = b;
}

// ---------------- HMMA GEMM: out = A @ W^T + bias ----------------
// BM=128, BN=128, BK=32, 256 threads (8 warps as 2x4), cp.async double buffer.
// Row pitch 40 halves (80B): 8 consecutive rows cover all 32 banks once ->
// conflict-free ldmatrix.
#define GP 40

template<bool DENSE>
__global__ __launch_bounds__(256) void hmma_gemm_kernel(
    float* __restrict__ outf, const float* __restrict__ dense_b,
    const float* __restrict__ bq, const float* __restrict__ bk,
    const float* __restrict__ bv)
{
    __shared__ __half sA[2][128 * GP];
    __shared__ __half sB[2][128 * GP];

    const int tid = threadIdx.x, lane = tid & 31, wid = tid >> 5;
    const int wm = wid & 1, wn = wid >> 1;
    const int m0 = blockIdx.y * 128, n0 = blockIdx.x * 128;
    const int z = DENSE ? 3 : blockIdx.z;

    const __half* W = g_Wh + z * (DMODEL * KDIM);
    const float* bias = DENSE ? dense_b : (z == 0 ? bq : z == 1 ? bk : bv);
    __half* outh = DENSE ? nullptr : (z == 0 ? g_Qh : z == 1 ? g_Kh : g_Vh);

    const uint32_t sbA = smem_u32(sA), sbB = smem_u32(sB);

    float acc[4][4][4];
    #pragma unroll
    for (int mi = 0; mi < 4; mi++)
        #pragma unroll
        for (int g = 0; g < 4; g++)
            #pragma unroll
            for (int e = 0; e < 4; e++) acc[mi][g][e] = 0.0f;

    const uint32_t abase = ((((lane >> 3) & 1) * 8 + (lane & 7)) * GP) * 2 + ((lane >> 4) & 1) * 16;
    const uint32_t kbase = ((((lane >> 4) & 1) * 8 + (lane & 7)) * GP) * 2 + ((lane >> 3) & 1) * 16;

    // stage loader (one cp.async group per stage: 2 A + 2 B chunks per thread)
    #define LOAD_STAGE(kt, buf) do {                                                        \
        const int k0_ = (kt) * 32;                                                          \
        _Pragma("unroll")                                                                   \
        for (int l = 0; l < 2; l++) {                                                       \
            int idx = tid + l * 256;                                                        \
            int r = idx >> 2, c = idx & 3;                                                  \
            const __half* asrc = DENSE                                                      \
                ? (g_Ch + (k0_ >> 6) * (SEQ * HD) + (m0 + r) * HD + (k0_ & 63) + c * 8)     \
                : (g_Xh + (m0 + r) * KDIM + k0_ + c * 8);                                   \
            cp16(sbA + ((buf) * 128 * GP + r * GP) * 2 + c * 16, asrc);                     \
            cp16(sbB + ((buf) * 128 * GP + r * GP) * 2 + c * 16,                            \
                 W + (n0 + r) * KDIM + k0_ + c * 8);                                        \
        }                                                                                   \
        cp_commit();                                                                        \
    } while (0)

    LOAD_STAGE(0, 0);

    for (int kt = 0; kt < KDIM / 32; kt++) {
        const int buf = kt & 1;
        if (kt + 1 < KDIM / 32) { LOAD_STAGE(kt + 1, buf ^ 1); cp_wait1(); }
        else cp_wait0();
        __syncthreads();

        const uint32_t aw = sbA + (buf * 128 * GP + wm * 64 * GP) * 2;
        const uint32_t bw = sbB + (buf * 128 * GP + wn * 32 * GP) * 2;
        #pragma unroll
        for (int t = 0; t < 2; t++) {
            uint32_t Af[4][4];
            #pragma unroll
            for (int mi = 0; mi < 4; mi++)
                ldsm4(Af[mi], aw + (mi * 16 * GP) * 2 + t * 32 + abase);
            uint32_t Bf[2][4];
            #pragma unroll
            for (int bi = 0; bi < 2; bi++)
                ldsm4(Bf[bi], bw + (bi * 16 * GP) * 2 + t * 32 + kbase);
            #pragma unroll
            for (int mi = 0; mi < 4; mi++)
                #pragma unroll
                for (int bi = 0; bi < 2; bi++) {
                    mma16816(acc[mi][bi * 2],     Af[mi], Bf[bi]);
                    mma16816(acc[mi][bi * 2 + 1], Af[mi], Bf[bi] + 2);
                }
        }
        __syncthreads();
    }
    #undef LOAD_STAGE

    // epilogue
    const int qr = lane >> 2, qc = (lane & 3) << 1;
    #pragma unroll
    for (int mi = 0; mi < 4; mi++) {
        int mrow = m0 + wm * 64 + mi * 16 + qr;
        #pragma unroll
        for (int g = 0; g < 4; g++) {
            int n = n0 + wn * 32 + g * 8 + qc;
            float b0 = bias[n], b1 = bias[n + 1];
            if (DENSE) {
                float2 u0 = { acc[mi][g][0] + b0, acc[mi][g][1] + b1 };
                float2 u1 = { acc[mi][g][2] + b0, acc[mi][g][3] + b1 };
                *reinterpret_cast<float2*>(outf + mrow * DMODEL + n)       = u0;
                *reinterpret_cast<float2*>(outf + (mrow + 8) * DMODEL + n) = u1;
            } else {
                uint32_t u0 = pack_h2(acc[mi][g][0] + b0, acc[mi][g][1] + b1);
                uint32_t u1 = pack_h2(acc[mi][g][2] + b0, acc[mi][g][3] + b1);
                *reinterpret_cast<uint32_t*>(outh + mrow * DMODEL + n)       = u0;
                *reinterpret_cast<uint32_t*>(outh + (mrow + 8) * DMODEL + n) = u1;
            }
        }
    }
}

// ---------------- fp16 mma.sync flash attention ----------------
#define QPITCH 144
#define OFF_Q   0
#define OFF_K0  (128 * QPITCH)
#define OFF_K1  (OFF_K0 + 64 * QPITCH)
#define OFF_V0  (OFF_K1 + 64 * QPITCH)
#define OFF_V1  (OFF_V0 + 64 * QPITCH)
#define FL_SMEM (OFF_V1 + 64 * QPITCH)

__global__ void __launch_bounds__(256, 1) flash_mma_kernel()
{
    extern __shared__ __align__(128) char smem[];
    const uint32_t sb = smem_u32(smem);
    const int tid  = threadIdx.x;
    const int wid  = tid >> 5;
    const int lane = tid & 31;
    const int h    = blockIdx.y;
    const int q0   = blockIdx.x * BM;
    const __half* Qg = g_Qh + h * (SEQ * HD);
    const __half* Kg = g_Kh + h * (SEQ * HD);
    const __half* Vg = g_Vh + h * (SEQ * HD);

    {
        int r = tid >> 1, c0 = (tid & 1) * 32;
        const uint4* src = reinterpret_cast<const uint4*>(Qg + (q0 + r) * HD + c0);
        char* dst = smem + OFF_Q + r * QPITCH + c0 * 2;
        #pragma unroll
        for (int k = 0; k < 4; k++)
            reinterpret_cast<uint4*>(dst)[k] = src[k];
    }
    #pragma unroll
    for (int l = 0; l < 2; l++) {
        int idx = tid + l * 256;
        int r = idx >> 3, ch = (idx & 7) << 3;
        cp16(sb + OFF_K0 + r * QPITCH + ch * 2, Kg + r * HD + ch);
        cp16(sb + OFF_V0 + r * QPITCH + ch * 2, Vg + r * HD + ch);
    }
    cp_commit();
    cp_wait0();
    __syncthreads();

    const int qb = wid * 16;
    const uint32_t abase = ((((lane >> 3) & 1) * 8 + (lane & 7)) * QPITCH) + (((lane >> 4) & 1) * 16);
    const uint32_t kbase = ((((lane >> 4) & 1) * 8 + (lane & 7)) * QPITCH) + (((lane >> 3) & 1) * 16);

    uint32_t Aq[4][4];
    #pragma unroll
    for (int t = 0; t < 4; t++)
        ldsm4(Aq[t], sb + OFF_Q + qb * QPITCH + t * 32 + abase);

    float Oacc[8][4];
    #pragma unroll
    for (int j = 0; j < 8; j++)
        #pragma unroll
        for (int e = 0; e < 4; e++) Oacc[j][e] = 0.0f;

    const int row0 = q0 + qb + (lane >> 2);
    const int row1 = row0 + 8;
    const int qv = lane & 3;
    float lsum0 = 0.0f, lsum1 = 0.0f;

    for (int i = 0; i < NKB; i++) {
        const uint32_t kcur = sb + ((i & 1) ? OFF_K1 : OFF_K0);
        const uint32_t vcur = sb + ((i & 1) ? OFF_V1 : OFF_V0);

        if (i + 1 < NKB) {
            const uint32_t kn = sb + ((i & 1) ? OFF_K0 : OFF_K1);
            const uint32_t vn = sb + ((i & 1) ? OFF_V0 : OFF_V1);
            const __half* Kn = Kg + (i + 1) * BN * HD;
            const __half* Vn = Vg + (i + 1) * BN * HD;
            #pragma unroll
            for (int l = 0; l < 2; l++) {
                int idx = tid + l * 256;
                int r = idx >> 3, ch = (idx & 7) << 3;
                cp16(kn + r * QPITCH + ch * 2, Kn + r * HD + ch);
                cp16(vn + r * QPITCH + ch * 2, Vn + r * HD + ch);
            }
            cp_commit();
        }

        uint2 m0 = *reinterpret_cast<const uint2*>(g_mb + row0 * NW + (i << 1));
        uint2 m1 = *reinterpret_cast<const uint2*>(g_mb + row1 * NW + (i << 1));

        float S[8][4];
        #pragma unroll
        for (int j = 0; j < 8; j++)
            #pragma unroll
            for (int e = 0; e < 4; e++) S[j][e] = 0.0f;

        #pragma unroll
        for (int jp = 0; jp < 4; jp++) {
            #pragma unroll
            for (int t = 0; t < 4; t++) {
                uint32_t B[4];
                ldsm4(B, kcur + jp * (16 * QPITCH) + t * 32 + kbase);
                mma16816(S[2 * jp],     Aq[t], B);
                mma16816(S[2 * jp + 1], Aq[t], B + 2);
            }
        }

        uint32_t Ap[4][4];
        #pragma unroll
        for (int j = 0; j < 8; j++) {
            unsigned w0 = (j < 4) ? m0.x : m0.y;
            unsigned w1 = (j < 4) ? m1.x : m1.y;
            int p0 = ((j & 3) << 3) + (qv << 1);
            float e0 = ((w0 >> p0) & 1u)       ? 0.0f : fexp8(S[j][0]);
            float e1 = ((w0 >> (p0 + 1)) & 1u) ? 0.0f : fexp8(S[j][1]);
            float e2 = ((w1 >> p0) & 1u)       ? 0.0f : fexp8(S[j][2]);
            float e3 = ((w1 >> (p0 + 1)) & 1u) ? 0.0f : fexp8(S[j][3]);
            lsum0 += e0 + e1;
            lsum1 += e2 + e3;
            int t = j >> 1;
            if ((j & 1) == 0) { Ap[t][0] = pack_h2(e0, e1); Ap[t][1] = pack_h2(e2, e3); }
            else              { Ap[t][2] = pack_h2(e0, e1); Ap[t][3] = pack_h2(e2, e3); }
        }

        #pragma unroll
        for (int jp = 0; jp < 4; jp++) {
            #pragma unroll
            for (int t = 0; t < 4; t++) {
                uint32_t B[4];
                ldsm4t(B, vcur + t * (16 * QPITCH) + jp * 32 + abase);
                mma16816(Oacc[2 * jp],     Ap[t], B);
                mma16816(Oacc[2 * jp + 1], Ap[t], B + 2);
            }
        }

        if (i + 1 < NKB) cp_wait0();
        __syncthreads();
    }

    lsum0 += __shfl_xor_sync(0xffffffffu, lsum0, 1);
    lsum0 += __shfl_xor_sync(0xffffffffu, lsum0, 2);
    lsum1 += __shfl_xor_sync(0xffffffffu, lsum1, 1);
    lsum1 += __shfl_xor_sync(0xffffffffu, lsum1, 2);
    float inv0 = 1.0f / lsum0;
    float inv1 = 1.0f / lsum1;

    __half* C0 = g_Ch + h * (SEQ * HD) + row0 * HD;
    __half* C1 = g_Ch + h * (SEQ * HD) + row1 * HD;
    #pragma unroll
    for (int j = 0; j < 8; j++) {
        int c = 8 * j + (qv << 1);
        *reinterpret_cast<uint32_t*>(C0 + c) = pack_h2(Oacc[j][0] * inv0, Oacc[j][1] * inv0);
        *reinterpret_cast<uint32_t*>(C1 + c) = pack_h2(Oacc[j][2] * inv1, Oacc[j][3] * inv1);
    }
}

// ---------------- launch ----------------
extern "C" void kernel_launch(void* const* d_in, const int* in_sizes, int n_in,
                              void* d_out, int out_size)
{
    (void)in_sizes; (void)n_in; (void)out_size;
    const float* x  = (const float*)d_in[0];
    const int*   mk = (const int*)d_in[1];
    const float* bq = (const float*)d_in[3];
    const float* bk = (const float*)d_in[5];
    const float* bv = (const float*)d_in[7];
    const float* db = (const float*)d_in[9];
    const float* wq = (const float*)d_in[2];
    const float* wk = (const float*)d_in[4];
    const float* wv = (const float*)d_in[6];
    const float* dw = (const float*)d_in[8];
    float* out = (float*)d_out;

    cudaFuncSetAttribute(flash_mma_kernel,
                         cudaFuncAttributeMaxDynamicSharedMemorySize, FL_SMEM);

    convert_kernel<<<3072, 256>>>(x, wq, wk, wv, dw);
    hmma_gemm_kernel<false><<<dim3(DMODEL / 128, SEQ / 128, 3), 256>>>(nullptr, nullptr, bq, bk, bv);
    mask_pack_kernel<<<(SEQ * SEQ) / 256, 256>>>(mk);
    flash_mma_kernel<<<dim3(SEQ / BM, NH), 256, FL_SMEM>>>();
    hmma_gemm_kernel<true><<<dim3(DMODEL / 128, SEQ / 128), 256>>>(out, db, nullptr, nullptr, nullptr);
}

// round 7
// speedup vs baseline: 3.5658x; 1.0160x over previous
#include <cuda_runtime.h>
#include <cuda_fp16.h>
#include <cstdint>

#define SEQ    4096
#define DMODEL 512
#define NH     8
#define HD     64
#define KDIM   512
#define NW     (SEQ / 32)   // 128 mask words per row

#define BM 64
#define BN 64
#define NKB (SEQ / BN)

// ---------------- scratch (device globals; no allocation allowed) ----------------
__device__ __half   g_Xh[SEQ * KDIM];          // fp16 copy of x
__device__ __half   g_Wh[4 * DMODEL * KDIM];   // wq, wk, wv, dense (fp16)
__device__ __half   g_Qh[SEQ * DMODEL];
__device__ __half   g_Kh[SEQ * DMODEL];
__device__ __half   g_Vh[SEQ * DMODEL];
__device__ __half   g_Ch[SEQ * DMODEL];        // context (head-major), fp16
__device__ unsigned g_mb[SEQ * NW];

// ================= helpers =================
__device__ __forceinline__ uint32_t smem_u32(const void* p) {
    uint32_t a;
    asm("{ .reg .u64 t; cvta.to.shared.u64 t, %1; cvt.u32.u64 %0, t; }" : "=r"(a) : "l"(p));
    return a;
}
__device__ __forceinline__ void cp16(uint32_t dst, const void* src) {
    asm volatile("cp.async.cg.shared.global [%0], [%1], 16;" :: "r"(dst), "l"(src));
}
__device__ __forceinline__ void cp_commit() { asm volatile("cp.async.commit_group;"); }
__device__ __forceinline__ void cp_wait0()  { asm volatile("cp.async.wait_group 0;" ::: "memory"); }
__device__ __forceinline__ void cp_wait1()  { asm volatile("cp.async.wait_group 1;" ::: "memory"); }

__device__ __forceinline__ void ldsm4(uint32_t* r, uint32_t addr) {
    asm volatile("ldmatrix.sync.aligned.m8n8.x4.shared.b16 {%0,%1,%2,%3}, [%4];"
        : "=r"(r[0]), "=r"(r[1]), "=r"(r[2]), "=r"(r[3]) : "r"(addr));
}
__device__ __forceinline__ void ldsm4t(uint32_t* r, uint32_t addr) {
    asm volatile("ldmatrix.sync.aligned.m8n8.x4.trans.shared.b16 {%0,%1,%2,%3}, [%4];"
        : "=r"(r[0]), "=r"(r[1]), "=r"(r[2]), "=r"(r[3]) : "r"(addr));
}
// D = A*B + D   (m16n8k16, f16 in, f32 accum)
__device__ __forceinline__ void mma16816(float* d, const uint32_t* a, const uint32_t* b) {
    asm volatile("mma.sync.aligned.m16n8k16.row.col.f32.f16.f16.f32 "
        "{%0,%1,%2,%3}, {%4,%5,%6,%7}, {%8,%9}, {%0,%1,%2,%3};"
        : "+f"(d[0]), "+f"(d[1]), "+f"(d[2]), "+f"(d[3])
        : "r"(a[0]), "r"(a[1]), "r"(a[2]), "r"(a[3]), "r"(b[0]), "r"(b[1]));
}
__device__ __forceinline__ uint32_t pack_h2(float a, float b) {
    __half2 h = __floats2half2_rn(a, b);
    return *reinterpret_cast<uint32_t*>(&h);
}
// exp(s * 0.125) via exp2 FFMA polynomial
__device__ __forceinline__ float fexp8(float s) {
    const float C = 0.125f * 1.4426950408889634f;
    float z = fmaf(s, C, 12582912.0f);
    float n = z - 12582912.0f;
    float r = fmaf(s, C, -n);
    float p = 1.3333558146e-3f;
    p = fmaf(p, r, 9.6181291076e-3f);
    p = fmaf(p, r, 5.5504108665e-2f);
    p = fmaf(p, r, 2.4022650696e-1f);
    p = fmaf(p, r, 6.9314718056e-1f);
    p = fmaf(p, r, 1.0f);
    return __int_as_float(__float_as_int(p) + (__float_as_int(z) << 23));
}

// ---------------- convert: x + 4 weight matrices -> fp16 ----------------
__global__ __launch_bounds__(256) void convert_kernel(
    const float* __restrict__ x,  const float* __restrict__ wq,
    const float* __restrict__ wk, const float* __restrict__ wv,
    const float* __restrict__ dw)
{
    int f4 = blockIdx.x * 256 + threadIdx.x;   // 0 .. 786431
    const float4* src; __half* dst; int off;
    if (f4 < 524288) { src = (const float4*)x; off = f4; dst = g_Xh; }
    else {
        int t = f4 - 524288;
        int w = t >> 16; off = t & 65535;
        src = (const float4*)(w == 0 ? wq : w == 1 ? wk : w == 2 ? wv : dw);
        dst = g_Wh + w * (DMODEL * KDIM);
    }
    float4 v = src[off];
    uint2 u = { pack_h2(v.x, v.y), pack_h2(v.z, v.w) };
    *reinterpret_cast<uint2*>(dst + off * 4) = u;
}

// ---------------- mask pack: int32 [S,S] -> bitmask ----------------
__global__ void mask_pack_kernel(const int* __restrict__ mask)
{
    int gid = blockIdx.x * 256 + threadIdx.x;
    int v = mask[gid];
    unsigned b = __ballot_sync(0xffffffffu, v != 0);
    if ((threadIdx.x & 31) == 0) g_mb[gid >> 5] = b;
}

// ---------------- HMMA GEMM: out = A @ W^T + bias ----------------
// BM=128, BN=128, BK=32, 256 threads (8 warps as 2x4), cp.async double buffer.
// Row pitch 40 halves (80B): 8 consecutive rows cover all 32 banks once ->
// conflict-free ldmatrix.
#define GP 40

template<bool DENSE>
__global__ __launch_bounds__(256) void hmma_gemm_kernel(
    float* __restrict__ outf, const float* __restrict__ dense_b,
    const float* __restrict__ bq, const float* __restrict__ bk,
    const float* __restrict__ bv)
{
    __shared__ __half sA[2][128 * GP];
    __shared__ __half sB[2][128 * GP];

    const int tid = threadIdx.x, lane = tid & 31, wid = tid >> 5;
    const int wm = wid & 1, wn = wid >> 1;
    const int m0 = blockIdx.y * 128, n0 = blockIdx.x * 128;
    const int z = DENSE ? 3 : blockIdx.z;

    const __half* W = g_Wh + z * (DMODEL * KDIM);
    const float* bias = DENSE ? dense_b : (z == 0 ? bq : z == 1 ? bk : bv);
    __half* outh = DENSE ? nullptr : (z == 0 ? g_Qh : z == 1 ? g_Kh : g_Vh);

    const uint32_t sbA = smem_u32(sA), sbB = smem_u32(sB);

    float acc[4][4][4];
    #pragma unroll
    for (int mi = 0; mi < 4; mi++)
        #pragma unroll
        for (int g = 0; g < 4; g++)
            #pragma unroll
            for (int e = 0; e < 4; e++) acc[mi][g][e] = 0.0f;

    const uint32_t abase = ((((lane >> 3) & 1) * 8 + (lane & 7)) * GP) * 2 + ((lane >> 4) & 1) * 16;
    const uint32_t kbase = ((((lane >> 4) & 1) * 8 + (lane & 7)) * GP) * 2 + ((lane >> 3) & 1) * 16;

    #define LOAD_STAGE(kt, buf) do {                                                        \
        const int k0_ = (kt) * 32;                                                          \
        _Pragma("unroll")                                                                   \
        for (int l = 0; l < 2; l++) {                                                       \
            int idx = tid + l * 256;                                                        \
            int r = idx >> 2, c = idx & 3;                                                  \
            const __half* asrc = DENSE                                                      \
                ? (g_Ch + (k0_ >> 6) * (SEQ * HD) + (m0 + r) * HD + (k0_ & 63) + c * 8)     \
                : (g_Xh + (m0 + r) * KDIM + k0_ + c * 8);                                   \
            cp16(sbA + ((buf) * 128 * GP + r * GP) * 2 + c * 16, asrc);                     \
            cp16(sbB + ((buf) * 128 * GP + r * GP) * 2 + c * 16,                            \
                 W + (n0 + r) * KDIM + k0_ + c * 8);                                        \
        }                                                                                   \
        cp_commit();                                                                        \
    } while (0)

    LOAD_STAGE(0, 0);

    for (int kt = 0; kt < KDIM / 32; kt++) {
        const int buf = kt & 1;
        if (kt + 1 < KDIM / 32) { LOAD_STAGE(kt + 1, buf ^ 1); cp_wait1(); }
        else cp_wait0();
        __syncthreads();

        const uint32_t aw = sbA + (buf * 128 * GP + wm * 64 * GP) * 2;
        const uint32_t bw = sbB + (buf * 128 * GP + wn * 32 * GP) * 2;
        #pragma unroll
        for (int t = 0; t < 2; t++) {
            uint32_t Af[4][4];
            #pragma unroll
            for (int mi = 0; mi < 4; mi++)
                ldsm4(Af[mi], aw + (mi * 16 * GP) * 2 + t * 32 + abase);
            uint32_t Bf[2][4];
            #pragma unroll
            for (int bi = 0; bi < 2; bi++)
                ldsm4(Bf[bi], bw + (bi * 16 * GP) * 2 + t * 32 + kbase);
            #pragma unroll
            for (int mi = 0; mi < 4; mi++)
                #pragma unroll
                for (int bi = 0; bi < 2; bi++) {
                    mma16816(acc[mi][bi * 2],     Af[mi], Bf[bi]);
                    mma16816(acc[mi][bi * 2 + 1], Af[mi], Bf[bi] + 2);
                }
        }
        __syncthreads();
    }
    #undef LOAD_STAGE

    // epilogue
    const int qr = lane >> 2, qc = (lane & 3) << 1;
    #pragma unroll
    for (int mi = 0; mi < 4; mi++) {
        int mrow = m0 + wm * 64 + mi * 16 + qr;
        #pragma unroll
        for (int g = 0; g < 4; g++) {
            int n = n0 + wn * 32 + g * 8 + qc;
            float b0 = bias[n], b1 = bias[n + 1];
            if (DENSE) {
                float2 u0 = { acc[mi][g][0] + b0, acc[mi][g][1] + b1 };
                float2 u1 = { acc[mi][g][2] + b0, acc[mi][g][3] + b1 };
                *reinterpret_cast<float2*>(outf + mrow * DMODEL + n)       = u0;
                *reinterpret_cast<float2*>(outf + (mrow + 8) * DMODEL + n) = u1;
            } else {
                uint32_t u0 = pack_h2(acc[mi][g][0] + b0, acc[mi][g][1] + b1);
                uint32_t u1 = pack_h2(acc[mi][g][2] + b0, acc[mi][g][3] + b1);
                *reinterpret_cast<uint32_t*>(outh + mrow * DMODEL + n)       = u0;
                *reinterpret_cast<uint32_t*>(outh + (mrow + 8) * DMODEL + n) = u1;
            }
        }
    }
}

// ---------------- fp16 mma.sync flash attention ----------------
// BM=64, 128 threads (4 warps x 16 q-rows), 3 CTAs/SM for latency hiding.
#define QPITCH 144
#define OFF_Q   0
#define OFF_K0  (64 * QPITCH)
#define OFF_K1  (OFF_K0 + 64 * QPITCH)
#define OFF_V0  (OFF_K1 + 64 * QPITCH)
#define OFF_V1  (OFF_V0 + 64 * QPITCH)
#define FL_SMEM (OFF_V1 + 64 * QPITCH)         // 5*64*144 = 46080 B

__global__ void __launch_bounds__(128, 3) flash_mma_kernel()
{
    extern __shared__ __align__(128) char smem[];
    const uint32_t sb = smem_u32(smem);
    const int tid  = threadIdx.x;
    const int wid  = tid >> 5;
    const int lane = tid & 31;
    const int h    = blockIdx.y;
    const int q0   = blockIdx.x * BM;
    const __half* Qg = g_Qh + h * (SEQ * HD);
    const __half* Kg = g_Kh + h * (SEQ * HD);
    const __half* Vg = g_Vh + h * (SEQ * HD);

    // ---- prologue: Q -> smem (padded), K0/V0 via cp.async ----
    {
        int r = tid >> 1, c0 = (tid & 1) * 32;    // 64 rows, 32 halves each
        const uint4* src = reinterpret_cast<const uint4*>(Qg + (q0 + r) * HD + c0);
        char* dst = smem + OFF_Q + r * QPITCH + c0 * 2;
        #pragma unroll
        for (int k = 0; k < 4; k++)
            reinterpret_cast<uint4*>(dst)[k] = src[k];
    }
    #pragma unroll
    for (int l = 0; l < 4; l++) {
        int idx = tid + l * 128;                  // 0..511
        int r = idx >> 3, ch = (idx & 7) << 3;
        cp16(sb + OFF_K0 + r * QPITCH + ch * 2, Kg + r * HD + ch);
        cp16(sb + OFF_V0 + r * QPITCH + ch * 2, Vg + r * HD + ch);
    }
    cp_commit();
    cp_wait0();
    __syncthreads();

    const int qb = wid * 16;
    const uint32_t abase = ((((lane >> 3) & 1) * 8 + (lane & 7)) * QPITCH) + (((lane >> 4) & 1) * 16);
    const uint32_t kbase = ((((lane >> 4) & 1) * 8 + (lane & 7)) * QPITCH) + (((lane >> 3) & 1) * 16);

    uint32_t Aq[4][4];
    #pragma unroll
    for (int t = 0; t < 4; t++)
        ldsm4(Aq[t], sb + OFF_Q + qb * QPITCH + t * 32 + abase);

    float Oacc[8][4];
    #pragma unroll
    for (int j = 0; j < 8; j++)
        #pragma unroll
        for (int e = 0; e < 4; e++) Oacc[j][e] = 0.0f;

    const int row0 = q0 + qb + (lane >> 2);
    const int row1 = row0 + 8;
    const int qv = lane & 3;
    float lsum0 = 0.0f, lsum1 = 0.0f;

    for (int i = 0; i < NKB; i++) {
        const uint32_t kcur = sb + ((i & 1) ? OFF_K1 : OFF_K0);
        const uint32_t vcur = sb + ((i & 1) ? OFF_V1 : OFF_V0);

        // prefetch next K/V
        if (i + 1 < NKB) {
            const uint32_t kn = sb + ((i & 1) ? OFF_K0 : OFF_K1);
            const uint32_t vn = sb + ((i & 1) ? OFF_V0 : OFF_V1);
            const __half* Kn = Kg + (i + 1) * BN * HD;
            const __half* Vn = Vg + (i + 1) * BN * HD;
            #pragma unroll
            for (int l = 0; l < 4; l++) {
                int idx = tid + l * 128;
                int r = idx >> 3, ch = (idx & 7) << 3;
                cp16(kn + r * QPITCH + ch * 2, Kn + r * HD + ch);
                cp16(vn + r * QPITCH + ch * 2, Vn + r * HD + ch);
            }
            cp_commit();
        }

        uint2 m0 = *reinterpret_cast<const uint2*>(g_mb + row0 * NW + (i << 1));
        uint2 m1 = *reinterpret_cast<const uint2*>(g_mb + row1 * NW + (i << 1));

        // ---- S = Q K^T ----
        float S[8][4];
        #pragma unroll
        for (int j = 0; j < 8; j++)
            #pragma unroll
            for (int e = 0; e < 4; e++) S[j][e] = 0.0f;

        #pragma unroll
        for (int jp = 0; jp < 4; jp++) {
            #pragma unroll
            for (int t = 0; t < 4; t++) {
                uint32_t B[4];
                ldsm4(B, kcur + jp * (16 * QPITCH) + t * 32 + kbase);
                mma16816(S[2 * jp],     Aq[t], B);
                mma16816(S[2 * jp + 1], Aq[t], B + 2);
            }
        }

        // ---- softmax (no max-shift; masked -> exact 0) + pack P A-frags ----
        uint32_t Ap[4][4];
        #pragma unroll
        for (int j = 0; j < 8; j++) {
            unsigned w0 = (j < 4) ? m0.x : m0.y;
            unsigned w1 = (j < 4) ? m1.x : m1.y;
            int p0 = ((j & 3) << 3) + (qv << 1);
            float e0 = ((w0 >> p0) & 1u)       ? 0.0f : fexp8(S[j][0]);
            float e1 = ((w0 >> (p0 + 1)) & 1u) ? 0.0f : fexp8(S[j][1]);
            float e2 = ((w1 >> p0) & 1u)       ? 0.0f : fexp8(S[j][2]);
            float e3 = ((w1 >> (p0 + 1)) & 1u) ? 0.0f : fexp8(S[j][3]);
            lsum0 += e0 + e1;
            lsum1 += e2 + e3;
            int t = j >> 1;
            if ((j & 1) == 0) { Ap[t][0] = pack_h2(e0, e1); Ap[t][1] = pack_h2(e2, e3); }
            else              { Ap[t][2] = pack_h2(e0, e1); Ap[t][3] = pack_h2(e2, e3); }
        }

        // ---- O += P V ----
        #pragma unroll
        for (int jp = 0; jp < 4; jp++) {
            #pragma unroll
            for (int t = 0; t < 4; t++) {
                uint32_t B[4];
                ldsm4t(B, vcur + t * (16 * QPITCH) + jp * 32 + abase);
                mma16816(Oacc[2 * jp],     Ap[t], B);
                mma16816(Oacc[2 * jp + 1], Ap[t], B + 2);
            }
        }

        if (i + 1 < NKB) cp_wait0();
        __syncthreads();
    }

    // ---- epilogue ----
    lsum0 += __shfl_xor_sync(0xffffffffu, lsum0, 1);
    lsum0 += __shfl_xor_sync(0xffffffffu, lsum0, 2);
    lsum1 += __shfl_xor_sync(0xffffffffu, lsum1, 1);
    lsum1 += __shfl_xor_sync(0xffffffffu, lsum1, 2);
    float inv0 = 1.0f / lsum0;
    float inv1 = 1.0f / lsum1;

    __half* C0 = g_Ch + h * (SEQ * HD) + row0 * HD;
    __half* C1 = g_Ch + h * (SEQ * HD) + row1 * HD;
    #pragma unroll
    for (int j = 0; j < 8; j++) {
        int c = 8 * j + (qv << 1);
        *reinterpret_cast<uint32_t*>(C0 + c) = pack_h2(Oacc[j][0] * inv0, Oacc[j][1] * inv0);
        *reinterpret_cast<uint32_t*>(C1 + c) = pack_h2(Oacc[j][2] * inv1, Oacc[j][3] * inv1);
    }
}

// ---------------- launch ----------------
extern "C" void kernel_launch(void* const* d_in, const int* in_sizes, int n_in,
                              void* d_out, int out_size)
{
    (void)in_sizes; (void)n_in; (void)out_size;
    const float* x  = (const float*)d_in[0];
    const int*   mk = (const int*)d_in[1];
    const float* wq = (const float*)d_in[2];
    const float* bq = (const float*)d_in[3];
    const float* wk = (const float*)d_in[4];
    const float* bk = (const float*)d_in[5];
    const float* wv = (const float*)d_in[6];
    const float* bv = (const float*)d_in[7];
    const float* dw = (const float*)d_in[8];
    const float* db = (const float*)d_in[9];
    float* out = (float*)d_out;

    cudaFuncSetAttribute(flash_mma_kernel,
                         cudaFuncAttributeMaxDynamicSharedMemorySize, FL_SMEM);

    convert_kernel<<<3072, 256>>>(x, wq, wk, wv, dw);
    hmma_gemm_kernel<false><<<dim3(DMODEL / 128, SEQ / 128, 3), 256>>>(nullptr, nullptr, bq, bk, bv);
    mask_pack_kernel<<<(SEQ * SEQ) / 256, 256>>>(mk);
    flash_mma_kernel<<<dim3(SEQ / BM, NH), 128, FL_SMEM>>>();
    hmma_gemm_kernel<true><<<dim3(DMODEL / 128, SEQ / 128), 256>>>(out, db, nullptr, nullptr, nullptr);
}

// round 8
// speedup vs baseline: 4.7525x; 1.3328x over previous
#include <cuda_runtime.h>
#include <cuda_fp16.h>
#include <cstdint>

#define SEQ    4096
#define DMODEL 512
#define NH     8
#define HD     64
#define KDIM   512
#define NW     (SEQ / 32)   // 128 mask words per row

#define BM 64
#define BN 64
#define NKB (SEQ / BN)

// ---------------- scratch (device globals; no allocation allowed) ----------------
__device__ __half   g_Xh[SEQ * KDIM];          // fp16 copy of x
__device__ __half   g_Wh[4 * DMODEL * KDIM];   // wq, wk, wv, dense (fp16)
__device__ __half   g_Qh[SEQ * DMODEL];
__device__ __half   g_Kh[SEQ * DMODEL];
__device__ __half   g_Vh[SEQ * DMODEL];
__device__ __half   g_Ch[SEQ * DMODEL];        // context (head-major), fp16
__device__ unsigned g_mb[SEQ * NW];

// ================= helpers =================
__device__ __forceinline__ uint32_t smem_u32(const void* p) {
    uint32_t a;
    asm("{ .reg .u64 t; cvta.to.shared.u64 t, %1; cvt.u32.u64 %0, t; }" : "=r"(a) : "l"(p));
    return a;
}
__device__ __forceinline__ void cp16(uint32_t dst, const void* src) {
    asm volatile("cp.async.cg.shared.global [%0], [%1], 16;" :: "r"(dst), "l"(src));
}
__device__ __forceinline__ void cp_commit() { asm volatile("cp.async.commit_group;"); }
__device__ __forceinline__ void cp_wait0()  { asm volatile("cp.async.wait_group 0;" ::: "memory"); }
__device__ __forceinline__ void cp_wait1()  { asm volatile("cp.async.wait_group 1;" ::: "memory"); }

__device__ __forceinline__ void ldsm4(uint32_t* r, uint32_t addr) {
    asm volatile("ldmatrix.sync.aligned.m8n8.x4.shared.b16 {%0,%1,%2,%3}, [%4];"
        : "=r"(r[0]), "=r"(r[1]), "=r"(r[2]), "=r"(r[3]) : "r"(addr));
}
__device__ __forceinline__ void ldsm4t(uint32_t* r, uint32_t addr) {
    asm volatile("ldmatrix.sync.aligned.m8n8.x4.trans.shared.b16 {%0,%1,%2,%3}, [%4];"
        : "=r"(r[0]), "=r"(r[1]), "=r"(r[2]), "=r"(r[3]) : "r"(addr));
}
// D = A*B + D   (m16n8k16, f16 in, f32 accum)
__device__ __forceinline__ void mma16816(float* d, const uint32_t* a, const uint32_t* b) {
    asm volatile("mma.sync.aligned.m16n8k16.row.col.f32.f16.f16.f32 "
        "{%0,%1,%2,%3}, {%4,%5,%6,%7}, {%8,%9}, {%0,%1,%2,%3};"
        : "+f"(d[0]), "+f"(d[1]), "+f"(d[2]), "+f"(d[3])
        : "r"(a[0]), "r"(a[1]), "r"(a[2]), "r"(a[3]), "r"(b[0]), "r"(b[1]));
}
__device__ __forceinline__ uint32_t pack_h2(float a, float b) {
    __half2 h = __floats2half2_rn(a, b);
    return *reinterpret_cast<uint32_t*>(&h);
}
// exp(s * 0.125) via exp2 FFMA polynomial
__device__ __forceinline__ float fexp8(float s) {
    const float C = 0.125f * 1.4426950408889634f;
    float z = fmaf(s, C, 12582912.0f);
    float n = z - 12582912.0f;
    float r = fmaf(s, C, -n);
    float p = 1.3333558146e-3f;
    p = fmaf(p, r, 9.6181291076e-3f);
    p = fmaf(p, r, 5.5504108665e-2f);
    p = fmaf(p, r, 2.4022650696e-1f);
    p = fmaf(p, r, 6.9314718056e-1f);
    p = fmaf(p, r, 1.0f);
    return __int_as_float(__float_as_int(p) + (__float_as_int(z) << 23));
}

// ---------------- convert: x + 4 weight matrices -> fp16 ----------------
__global__ __launch_bounds__(256) void convert_kernel(
    const float* __restrict__ x,  const float* __restrict__ wq,
    const float* __restrict__ wk, const float* __restrict__ wv,
    const float* __restrict__ dw)
{
    int f4 = blockIdx.x * 256 + threadIdx.x;   // 0 .. 786431
    const float4* src; __half* dst; int off;
    if (f4 < 524288) { src = (const float4*)x; off = f4; dst = g_Xh; }
    else {
        int t = f4 - 524288;
        int w = t >> 16; off = t & 65535;
        src = (const float4*)(w == 0 ? wq : w == 1 ? wk : w == 2 ? wv : dw);
        dst = g_Wh + w * (DMODEL * KDIM);
    }
    float4 v = src[off];
    uint2 u = { pack_h2(v.x, v.y), pack_h2(v.z, v.w) };
    *reinterpret_cast<uint2*>(dst + off * 4) = u;
}

// ---------------- mask pack: int32 [S,S] -> bitmask ----------------
__global__ void mask_pack_kernel(const int* __restrict__ mask)
{
    int gid = blockIdx.x * 256 + threadIdx.x;
    int v = mask[gid];
    unsigned b = __ballot_sync(0xffffffffu, v != 0);
    if ((threadIdx.x & 31) == 0) g_mb[gid >> 5] = b;
}

// ---------------- HMMA GEMM: out = A @ W^T + bias ----------------
#define GP 40

template<bool DENSE>
__global__ __launch_bounds__(256) void hmma_gemm_kernel(
    float* __restrict__ outf, const float* __restrict__ dense_b,
    const float* __restrict__ bq, const float* __restrict__ bk,
    const float* __restrict__ bv)
{
    __shared__ __half sA[2][128 * GP];
    __shared__ __half sB[2][128 * GP];

    const int tid = threadIdx.x, lane = tid & 31, wid = tid >> 5;
    const int wm = wid & 1, wn = wid >> 1;
    const int m0 = blockIdx.y * 128, n0 = blockIdx.x * 128;
    const int z = DENSE ? 3 : blockIdx.z;

    const __half* W = g_Wh + z * (DMODEL * KDIM);
    const float* bias = DENSE ? dense_b : (z == 0 ? bq : z == 1 ? bk : bv);
    __half* outh = DENSE ? nullptr : (z == 0 ? g_Qh : z == 1 ? g_Kh : g_Vh);

    const uint32_t sbA = smem_u32(sA), sbB = smem_u32(sB);

    float acc[4][4][4];
    #pragma unroll
    for (int mi = 0; mi < 4; mi++)
        #pragma unroll
        for (int g = 0; g < 4; g++)
            #pragma unroll
            for (int e = 0; e < 4; e++) acc[mi][g][e] = 0.0f;

    const uint32_t abase = ((((lane >> 3) & 1) * 8 + (lane & 7)) * GP) * 2 + ((lane >> 4) & 1) * 16;
    const uint32_t kbase = ((((lane >> 4) & 1) * 8 + (lane & 7)) * GP) * 2 + ((lane >> 3) & 1) * 16;

    #define LOAD_STAGE(kt, buf) do {                                                        \
        const int k0_ = (kt) * 32;                                                          \
        _Pragma("unroll")                                                                   \
        for (int l = 0; l < 2; l++) {                                                       \
            int idx = tid + l * 256;                                                        \
            int r = idx >> 2, c = idx & 3;                                                  \
            const __half* asrc = DENSE                                                      \
                ? (g_Ch + (k0_ >> 6) * (SEQ * HD) + (m0 + r) * HD + (k0_ & 63) + c * 8)     \
                : (g_Xh + (m0 + r) * KDIM + k0_ + c * 8);                                   \
            cp16(sbA + ((buf) * 128 * GP + r * GP) * 2 + c * 16, asrc);                     \
            cp16(sbB + ((buf) * 128 * GP + r * GP) * 2 + c * 16,                            \
                 W + (n0 + r) * KDIM + k0_ + c * 8);                                        \
        }                                                                                   \
        cp_commit();                                                                        \
    } while (0)

    LOAD_STAGE(0, 0);

    for (int kt = 0; kt < KDIM / 32; kt++) {
        const int buf = kt & 1;
        if (kt + 1 < KDIM / 32) { LOAD_STAGE(kt + 1, buf ^ 1); cp_wait1(); }
        else cp_wait0();
        __syncthreads();

        const uint32_t aw = sbA + (buf * 128 * GP + wm * 64 * GP) * 2;
        const uint32_t bw = sbB + (buf * 128 * GP + wn * 32 * GP) * 2;
        #pragma unroll
        for (int t = 0; t < 2; t++) {
            uint32_t Af[4][4];
            #pragma unroll
            for (int mi = 0; mi < 4; mi++)
                ldsm4(Af[mi], aw + (mi * 16 * GP) * 2 + t * 32 + abase);
            uint32_t Bf[2][4];
            #pragma unroll
            for (int bi = 0; bi < 2; bi++)
                ldsm4(Bf[bi], bw + (bi * 16 * GP) * 2 + t * 32 + kbase);
            #pragma unroll
            for (int mi = 0; mi < 4; mi++)
                #pragma unroll
                for (int bi = 0; bi < 2; bi++) {
                    mma16816(acc[mi][bi * 2],     Af[mi], Bf[bi]);
                    mma16816(acc[mi][bi * 2 + 1], Af[mi], Bf[bi] + 2);
                }
        }
        __syncthreads();
    }
    #undef LOAD_STAGE

    const int qr = lane >> 2, qc = (lane & 3) << 1;
    #pragma unroll
    for (int mi = 0; mi < 4; mi++) {
        int mrow = m0 + wm * 64 + mi * 16 + qr;
        #pragma unroll
        for (int g = 0; g < 4; g++) {
            int n = n0 + wn * 32 + g * 8 + qc;
            float b0 = bias[n], b1 = bias[n + 1];
            if (DENSE) {
                float2 u0 = { acc[mi][g][0] + b0, acc[mi][g][1] + b1 };
                float2 u1 = { acc[mi][g][2] + b0, acc[mi][g][3] + b1 };
                *reinterpret_cast<float2*>(outf + mrow * DMODEL + n)       = u0;
                *reinterpret_cast<float2*>(outf + (mrow + 8) * DMODEL + n) = u1;
            } else {
                uint32_t u0 = pack_h2(acc[mi][g][0] + b0, acc[mi][g][1] + b1);
                uint32_t u1 = pack_h2(acc[mi][g][2] + b0, acc[mi][g][3] + b1);
                *reinterpret_cast<uint32_t*>(outh + mrow * DMODEL + n)       = u0;
                *reinterpret_cast<uint32_t*>(outh + (mrow + 8) * DMODEL + n) = u1;
            }
        }
    }
}

// ---------------- fp16 mma.sync flash attention (software-pipelined) ----------------
// BM=64, 128 threads (4 warps x 16 q-rows), 4 CTAs/SM -> single wave (512 CTAs).
// Pipeline: iter i does softmax(i) on S produced by QK(i+1)-issue of iter i-1,
// then issues QK(i+1) + PV(i) back-to-back. K(j) lives in buf j&1; V(j) in buf j&1.
#define QPITCH 144
#define OFF_Q   0
#define OFF_K0  (64 * QPITCH)
#define OFF_K1  (OFF_K0 + 64 * QPITCH)
#define OFF_V0  (OFF_K1 + 64 * QPITCH)
#define OFF_V1  (OFF_V0 + 64 * QPITCH)
#define FL_SMEM (OFF_V1 + 64 * QPITCH)         // 5*64*144 = 46080 B

__global__ void __launch_bounds__(128, 4) flash_mma_kernel()
{
    extern __shared__ __align__(128) char smem[];
    const uint32_t sb = smem_u32(smem);
    const int tid  = threadIdx.x;
    const int wid  = tid >> 5;
    const int lane = tid & 31;
    const int h    = blockIdx.y;
    const int q0   = blockIdx.x * BM;
    const __half* Qg = g_Qh + h * (SEQ * HD);
    const __half* Kg = g_Kh + h * (SEQ * HD);
    const __half* Vg = g_Vh + h * (SEQ * HD);

    // ---- prologue: Q -> smem (padded); K0,V0 (group), K1 (group) ----
    {
        int r = tid >> 1, c0 = (tid & 1) * 32;
        const uint4* src = reinterpret_cast<const uint4*>(Qg + (q0 + r) * HD + c0);
        char* dst = smem + OFF_Q + r * QPITCH + c0 * 2;
        #pragma unroll
        for (int k = 0; k < 4; k++)
            reinterpret_cast<uint4*>(dst)[k] = src[k];
    }
    #pragma unroll
    for (int l = 0; l < 4; l++) {
        int idx = tid + l * 128;                  // 0..511
        int r = idx >> 3, ch = (idx & 7) << 3;
        cp16(sb + OFF_K0 + r * QPITCH + ch * 2, Kg + r * HD + ch);
        cp16(sb + OFF_V0 + r * QPITCH + ch * 2, Vg + r * HD + ch);
    }
    cp_commit();
    #pragma unroll
    for (int l = 0; l < 4; l++) {
        int idx = tid + l * 128;
        int r = idx >> 3, ch = (idx & 7) << 3;
        cp16(sb + OFF_K1 + r * QPITCH + ch * 2, Kg + BN * HD + r * HD + ch);
    }
    cp_commit();
    cp_wait0();
    __syncthreads();

    const int qb = wid * 16;
    const uint32_t abase = ((((lane >> 3) & 1) * 8 + (lane & 7)) * QPITCH) + (((lane >> 4) & 1) * 16);
    const uint32_t kbase = ((((lane >> 4) & 1) * 8 + (lane & 7)) * QPITCH) + (((lane >> 3) & 1) * 16);

    uint32_t Aq[4][4];
    #pragma unroll
    for (int t = 0; t < 4; t++)
        ldsm4(Aq[t], sb + OFF_Q + qb * QPITCH + t * 32 + abase);

    float Oacc[8][4];
    #pragma unroll
    for (int j = 0; j < 8; j++)
        #pragma unroll
        for (int e = 0; e < 4; e++) Oacc[j][e] = 0.0f;

    // ---- issue QK(0) from Kbuf0 ----
    float S[8][4];
    #pragma unroll
    for (int j = 0; j < 8; j++)
        #pragma unroll
        for (int e = 0; e < 4; e++) S[j][e] = 0.0f;
    #pragma unroll
    for (int jp = 0; jp < 4; jp++) {
        #pragma unroll
        for (int t = 0; t < 4; t++) {
            uint32_t B[4];
            ldsm4(B, sb + OFF_K0 + jp * (16 * QPITCH) + t * 32 + kbase);
            mma16816(S[2 * jp],     Aq[t], B);
            mma16816(S[2 * jp + 1], Aq[t], B + 2);
        }
    }
    __syncthreads();   // LDSM(K0) executed in all warps before iter-0 prefetch overwrites Kbuf0

    const int row0 = q0 + qb + (lane >> 2);
    const int row1 = row0 + 8;
    const int qv = lane & 3;
    float lsum0 = 0.0f, lsum1 = 0.0f;

    for (int i = 0; i < NKB; i++) {
        // --- prefetch K(i+2) -> kbuf[i&1], V(i+1) -> vbuf[(i+1)&1] ---
        if (i + 2 < NKB) {
            const uint32_t kn = sb + ((i & 1) ? OFF_K1 : OFF_K0);
            const __half* Kn = Kg + (i + 2) * BN * HD;
            #pragma unroll
            for (int l = 0; l < 4; l++) {
                int idx = tid + l * 128;
                int r = idx >> 3, ch = (idx & 7) << 3;
                cp16(kn + r * QPITCH + ch * 2, Kn + r * HD + ch);
            }
            cp_commit();
        }
        if (i + 1 < NKB) {
            const uint32_t vn = sb + (((i + 1) & 1) ? OFF_V1 : OFF_V0);
            const __half* Vn = Vg + (i + 1) * BN * HD;
            #pragma unroll
            for (int l = 0; l < 4; l++) {
                int idx = tid + l * 128;
                int r = idx >> 3, ch = (idx & 7) << 3;
                cp16(vn + r * QPITCH + ch * 2, Vn + r * HD + ch);
            }
            cp_commit();
        }

        uint2 m0 = *reinterpret_cast<const uint2*>(g_mb + row0 * NW + (i << 1));
        uint2 m1 = *reinterpret_cast<const uint2*>(g_mb + row1 * NW + (i << 1));

        // --- softmax(i): S was produced by QK issued a full iteration ago ---
        uint32_t Ap[4][4];
        #pragma unroll
        for (int j = 0; j < 8; j++) {
            unsigned w0 = (j < 4) ? m0.x : m0.y;
            unsigned w1 = (j < 4) ? m1.x : m1.y;
            int p0 = ((j & 3) << 3) + (qv << 1);
            float e0 = ((w0 >> p0) & 1u)       ? 0.0f : fexp8(S[j][0]);
            float e1 = ((w0 >> (p0 + 1)) & 1u) ? 0.0f : fexp8(S[j][1]);
            float e2 = ((w1 >> p0) & 1u)       ? 0.0f : fexp8(S[j][2]);
            float e3 = ((w1 >> (p0 + 1)) & 1u) ? 0.0f : fexp8(S[j][3]);
            lsum0 += e0 + e1;
            lsum1 += e2 + e3;
            int t = j >> 1;
            if ((j & 1) == 0) { Ap[t][0] = pack_h2(e0, e1); Ap[t][1] = pack_h2(e2, e3); }
            else              { Ap[t][2] = pack_h2(e0, e1); Ap[t][3] = pack_h2(e2, e3); }
        }

        // --- issue QK(i+1) from kbuf[(i+1)&1] (S regs recycled) ---
        if (i + 1 < NKB) {
            const uint32_t kcur = sb + (((i + 1) & 1) ? OFF_K1 : OFF_K0);
            #pragma unroll
            for (int j = 0; j < 8; j++)
                #pragma unroll
                for (int e = 0; e < 4; e++) S[j][e] = 0.0f;
            #pragma unroll
            for (int jp = 0; jp < 4; jp++) {
                #pragma unroll
                for (int t = 0; t < 4; t++) {
                    uint32_t B[4];
                    ldsm4(B, kcur + jp * (16 * QPITCH) + t * 32 + kbase);
                    mma16816(S[2 * jp],     Aq[t], B);
                    mma16816(S[2 * jp + 1], Aq[t], B + 2);
                }
            }
        }

        // --- PV(i) from vbuf[i&1] ---
        {
            const uint32_t vcur = sb + ((i & 1) ? OFF_V1 : OFF_V0);
            #pragma unroll
            for (int jp = 0; jp < 4; jp++) {
                #pragma unroll
                for (int t = 0; t < 4; t++) {
                    uint32_t B[4];
                    ldsm4t(B, vcur + t * (16 * QPITCH) + jp * 32 + abase);
                    mma16816(Oacc[2 * jp],     Ap[t], B);
                    mma16816(Oacc[2 * jp + 1], Ap[t], B + 2);
                }
            }
        }

        cp_wait0();
        __syncthreads();
    }

    // ---- epilogue ----
    lsum0 += __shfl_xor_sync(0xffffffffu, lsum0, 1);
    lsum0 += __shfl_xor_sync(0xffffffffu, lsum0, 2);
    lsum1 += __shfl_xor_sync(0xffffffffu, lsum1, 1);
    lsum1 += __shfl_xor_sync(0xffffffffu, lsum1, 2);
    float inv0 = 1.0f / lsum0;
    float inv1 = 1.0f / lsum1;

    __half* C0 = g_Ch + h * (SEQ * HD) + row0 * HD;
    __half* C1 = g_Ch + h * (SEQ * HD) + row1 * HD;
    #pragma unroll
    for (int j = 0; j < 8; j++) {
        int c = 8 * j + (qv << 1);
        *reinterpret_cast<uint32_t*>(C0 + c) = pack_h2(Oacc[j][0] * inv0, Oacc[j][1] * inv0);
        *reinterpret_cast<uint32_t*>(C1 + c) = pack_h2(Oacc[j][2] * inv1, Oacc[j][3] * inv1);
    }
}

// ---------------- launch ----------------
extern "C" void kernel_launch(void* const* d_in, const int* in_sizes, int n_in,
                              void* d_out, int out_size)
{
    (void)in_sizes; (void)n_in; (void)out_size;
    const float* x  = (const float*)d_in[0];
    const int*   mk = (const int*)d_in[1];
    const float* wq = (const float*)d_in[2];
    const float* bq = (const float*)d_in[3];
    const float* wk = (const float*)d_in[4];
    const float* bk = (const float*)d_in[5];
    const float* wv = (const float*)d_in[6];
    const float* bv = (const float*)d_in[7];
    const float* dw = (const float*)d_in[8];
    const float* db = (const float*)d_in[9];
    float* out = (float*)d_out;

    cudaFuncSetAttribute(flash_mma_kernel,
                         cudaFuncAttributeMaxDynamicSharedMemorySize, FL_SMEM);

    convert_kernel<<<3072, 256>>>(x, wq, wk, wv, dw);
    hmma_gemm_kernel<false><<<dim3(DMODEL / 128, SEQ / 128, 3), 256>>>(nullptr, nullptr, bq, bk, bv);
    mask_pack_kernel<<<(SEQ * SEQ) / 256, 256>>>(mk);
    flash_mma_kernel<<<dim3(SEQ / BM, NH), 128, FL_SMEM>>>();
    hmma_gemm_kernel<true><<<dim3(DMODEL / 128, SEQ / 128), 256>>>(out, db, nullptr, nullptr, nullptr);
}

// round 10
// speedup vs baseline: 6.9606x; 1.4646x over previous
#include <cuda_runtime.h>
#include <cuda_fp16.h>
#include <cstdint>

#define SEQ    4096
#define DMODEL 512
#define NH     8
#define HD     64
#define KDIM   512
#define NW     (SEQ / 32)   // 128 mask words per row

#define BM 64
#define BN 64
#define NKB (SEQ / BN)

// 0.125 * log2(e): folded into Q projection so flash does exp2(S) directly
#define QSCALE 0.18033688011112042f

// ---------------- scratch (device globals; no allocation allowed) ----------------
__device__ __half   g_Xh[SEQ * KDIM];          // fp16 copy of x
__device__ __half   g_Wh[4 * DMODEL * KDIM];   // wq, wk, wv, dense (fp16)
__device__ __half   g_Qh[SEQ * DMODEL];        // pre-scaled by QSCALE
__device__ __half   g_Kh[SEQ * DMODEL];
__device__ __half   g_Vh[SEQ * DMODEL];
__device__ __half   g_Ch[SEQ * DMODEL];        // context (head-major), fp16
__device__ unsigned g_mb[SEQ * NW];

// ================= helpers =================
__device__ __forceinline__ uint32_t smem_u32(const void* p) {
    uint32_t a;
    asm("{ .reg .u64 t; cvta.to.shared.u64 t, %1; cvt.u32.u64 %0, t; }" : "=r"(a) : "l"(p));
    return a;
}
__device__ __forceinline__ void cp16(uint32_t dst, const void* src) {
    asm volatile("cp.async.cg.shared.global [%0], [%1], 16;" :: "r"(dst), "l"(src));
}
__device__ __forceinline__ void cp_commit() { asm volatile("cp.async.commit_group;"); }
__device__ __forceinline__ void cp_wait0()  { asm volatile("cp.async.wait_group 0;" ::: "memory"); }
__device__ __forceinline__ void cp_wait1()  { asm volatile("cp.async.wait_group 1;" ::: "memory"); }

__device__ __forceinline__ void ldsm4(uint32_t* r, uint32_t addr) {
    asm volatile("ldmatrix.sync.aligned.m8n8.x4.shared.b16 {%0,%1,%2,%3}, [%4];"
        : "=r"(r[0]), "=r"(r[1]), "=r"(r[2]), "=r"(r[3]) : "r"(addr));
}
__device__ __forceinline__ void ldsm4t(uint32_t* r, uint32_t addr) {
    asm volatile("ldmatrix.sync.aligned.m8n8.x4.trans.shared.b16 {%0,%1,%2,%3}, [%4];"
        : "=r"(r[0]), "=r"(r[1]), "=r"(r[2]), "=r"(r[3]) : "r"(addr));
}
// D = A*B + D   (m16n8k16, f16 in, f32 accum)
__device__ __forceinline__ void mma16816(float* d, const uint32_t* a, const uint32_t* b) {
    asm volatile("mma.sync.aligned.m16n8k16.row.col.f32.f16.f16.f32 "
        "{%0,%1,%2,%3}, {%4,%5,%6,%7}, {%8,%9}, {%0,%1,%2,%3};"
        : "+f"(d[0]), "+f"(d[1]), "+f"(d[2]), "+f"(d[3])
        : "r"(a[0]), "r"(a[1]), "r"(a[2]), "r"(a[3]), "r"(b[0]), "r"(b[1]));
}
__device__ __forceinline__ uint32_t pack_h2(float a, float b) {
    __half2 h = __floats2half2_rn(a, b);
    return *reinterpret_cast<uint32_t*>(&h);
}
// 2^x on the MUFU pipe (rt=8, own pipe; far fewer issue slots than FFMA poly)
__device__ __forceinline__ float ex2(float x) {
    float y;
    asm("ex2.approx.ftz.f32 %0, %1;" : "=f"(y) : "f"(x));
    return y;
}

// ---------------- convert: x + 4 weight matrices -> fp16 ----------------
__global__ __launch_bounds__(256) void convert_kernel(
    const float* __restrict__ x,  const float* __restrict__ wq,
    const float* __restrict__ wk, const float* __restrict__ wv,
    const float* __restrict__ dw)
{
    int f4 = blockIdx.x * 256 + threadIdx.x;   // 0 .. 786431
    const float4* src; __half* dst; int off;
    if (f4 < 524288) { src = (const float4*)x; off = f4; dst = g_Xh; }
    else {
        int t = f4 - 524288;
        int w = t >> 16; off = t & 65535;
        src = (const float4*)(w == 0 ? wq : w == 1 ? wk : w == 2 ? wv : dw);
        dst = g_Wh + w * (DMODEL * KDIM);
    }
    float4 v = src[off];
    uint2 u = { pack_h2(v.x, v.y), pack_h2(v.z, v.w) };
    *reinterpret_cast<uint2*>(dst + off * 4) = u;
}

// ---------------- mask pack: int32 [S,S] -> bitmask ----------------
__global__ void mask_pack_kernel(const int* __restrict__ mask)
{
    int gid = blockIdx.x * 256 + threadIdx.x;
    int v = mask[gid];
    unsigned b = __ballot_sync(0xffffffffu, v != 0);
    if ((threadIdx.x & 31) == 0) g_mb[gid >> 5] = b;
}

// ---------------- HMMA GEMM: out = (A @ W^T + bias) * scale ----------------
#define GP 40

template<bool DENSE>
__global__ __launch_bounds__(256) void hmma_gemm_kernel(
    float* __restrict__ outf, const float* __restrict__ dense_b,
    const float* __restrict__ bq, const float* __restrict__ bk,
    const float* __restrict__ bv)
{
    __shared__ __half sA[2][128 * GP];
    __shared__ __half sB[2][128 * GP];

    const int tid = threadIdx.x, lane = tid & 31, wid = tid >> 5;
    const int wm = wid & 1, wn = wid >> 1;
    const int m0 = blockIdx.y * 128, n0 = blockIdx.x * 128;
    const int z = DENSE ? 3 : blockIdx.z;

    const __half* W = g_Wh + z * (DMODEL * KDIM);
    const float* bias = DENSE ? dense_b : (z == 0 ? bq : z == 1 ? bk : bv);
    __half* outh = DENSE ? nullptr : (z == 0 ? g_Qh : z == 1 ? g_Kh : g_Vh);
    const float scale = (!DENSE && z == 0) ? QSCALE : 1.0f;

    const uint32_t sbA = smem_u32(sA), sbB = smem_u32(sB);

    float acc[4][4][4];
    #pragma unroll
    for (int mi = 0; mi < 4; mi++)
        #pragma unroll
        for (int g = 0; g < 4; g++)
            #pragma unroll
            for (int e = 0; e < 4; e++) acc[mi][g][e] = 0.0f;

    const uint32_t abase = ((((lane >> 3) & 1) * 8 + (lane & 7)) * GP) * 2 + ((lane >> 4) & 1) * 16;
    const uint32_t kbase = ((((lane >> 4) & 1) * 8 + (lane & 7)) * GP) * 2 + ((lane >> 3) & 1) * 16;

    #define LOAD_STAGE(kt, buf) do {                                                        \
        const int k0_ = (kt) * 32;                                                          \
        _Pragma("unroll")                                                                   \
        for (int l = 0; l < 2; l++) {                                                       \
            int idx = tid + l * 256;                                                        \
            int r = idx >> 2, c = idx & 3;                                                  \
            const __half* asrc = DENSE                                                      \
                ? (g_Ch + (k0_ >> 6) * (SEQ * HD) + (m0 + r) * HD + (k0_ & 63) + c * 8)     \
                : (g_Xh + (m0 + r) * KDIM + k0_ + c * 8);                                   \
            cp16(sbA + ((buf) * 128 * GP + r * GP) * 2 + c * 16, asrc);                     \
            cp16(sbB + ((buf) * 128 * GP + r * GP) * 2 + c * 16,                            \
                 W + (n0 + r) * KDIM + k0_ + c * 8);                                        \
        }                                                                                   \
        cp_commit();                                                                        \
    } while (0)

    LOAD_STAGE(0, 0);

    for (int kt = 0; kt < KDIM / 32; kt++) {
        const int buf = kt & 1;
        if (kt + 1 < KDIM / 32) { LOAD_STAGE(kt + 1, buf ^ 1); cp_wait1(); }
        else cp_wait0();
        __syncthreads();

        const uint32_t aw = sbA + (buf * 128 * GP + wm * 64 * GP) * 2;
        const uint32_t bw = sbB + (buf * 128 * GP + wn * 32 * GP) * 2;
        #pragma unroll
        for (int t = 0; t < 2; t++) {
            uint32_t Af[4][4];
            #pragma unroll
            for (int mi = 0; mi < 4; mi++)
                ldsm4(Af[mi], aw + (mi * 16 * GP) * 2 + t * 32 + abase);
            uint32_t Bf[2][4];
            #pragma unroll
            for (int bi = 0; bi < 2; bi++)
                ldsm4(Bf[bi], bw + (bi * 16 * GP) * 2 + t * 32 + kbase);
            #pragma unroll
            for (int mi = 0; mi < 4; mi++)
                #pragma unroll
                for (int bi = 0; bi < 2; bi++) {
                    mma16816(acc[mi][bi * 2],     Af[mi], Bf[bi]);
                    mma16816(acc[mi][bi * 2 + 1], Af[mi], Bf[bi] + 2);
                }
        }
        __syncthreads();
    }
    #undef LOAD_STAGE

    const int qr = lane >> 2, qc = (lane & 3) << 1;
    #pragma unroll
    for (int mi = 0; mi < 4; mi++) {
        int mrow = m0 + wm * 64 + mi * 16 + qr;
        #pragma unroll
        for (int g = 0; g < 4; g++) {
            int n = n0 + wn * 32 + g * 8 + qc;
            float b0 = bias[n], b1 = bias[n + 1];
            if (DENSE) {
                float2 u0 = { acc[mi][g][0] + b0, acc[mi][g][1] + b1 };
                float2 u1 = { acc[mi][g][2] + b0, acc[mi][g][3] + b1 };
                *reinterpret_cast<float2*>(outf + mrow * DMODEL + n)       = u0;
                *reinterpret_cast<float2*>(outf + (mrow + 8) * DMODEL + n) = u1;
            } else {
                uint32_t u0 = pack_h2((acc[mi][g][0] + b0) * scale, (acc[mi][g][1] + b1) * scale);
                uint32_t u1 = pack_h2((acc[mi][g][2] + b0) * scale, (acc[mi][g][3] + b1) * scale);
                *reinterpret_cast<uint32_t*>(outh + mrow * DMODEL + n)       = u0;
                *reinterpret_cast<uint32_t*>(outh + (mrow + 8) * DMODEL + n) = u1;
            }
        }
    }
}

// ---------------- fp16 mma.sync flash attention (pipelined, fused MMA loops) ----------------
// BM=64, 128 threads (4 warps x 16 q-rows), 4 CTAs/SM -> single wave (512 CTAs).
// Q pre-scaled by 0.125*log2(e): softmax is exp2(S) on the MUFU pipe.
// Iter i: softmax(i) on S from QK issued last iter; then fused loop issues
// QK(i+1) and PV(i) interleaved (independent chains hide HMMA/LDSM latency).
#define QPITCH 144
#define OFF_Q   0
#define OFF_K0  (64 * QPITCH)
#define OFF_K1  (OFF_K0 + 64 * QPITCH)
#define OFF_V0  (OFF_K1 + 64 * QPITCH)
#define OFF_V1  (OFF_V0 + 64 * QPITCH)
#define FL_SMEM (OFF_V1 + 64 * QPITCH)         // 5*64*144 = 46080 B

__global__ void __launch_bounds__(128, 4) flash_mma_kernel()
{
    extern __shared__ __align__(128) char smem[];
    const uint32_t sb = smem_u32(smem);
    const int tid  = threadIdx.x;
    const int wid  = tid >> 5;
    const int lane = tid & 31;
    const int h    = blockIdx.y;
    const int q0   = blockIdx.x * BM;
    const __half* Qg = g_Qh + h * (SEQ * HD);
    const __half* Kg = g_Kh + h * (SEQ * HD);
    const __half* Vg = g_Vh + h * (SEQ * HD);

    // ---- prologue: Q -> smem (padded); K0,V0 (group), K1 (group) ----
    {
        int r = tid >> 1, c0 = (tid & 1) * 32;
        const uint4* src = reinterpret_cast<const uint4*>(Qg + (q0 + r) * HD + c0);
        char* dst = smem + OFF_Q + r * QPITCH + c0 * 2;
        #pragma unroll
        for (int k = 0; k < 4; k++)
            reinterpret_cast<uint4*>(dst)[k] = src[k];
    }
    #pragma unroll
    for (int l = 0; l < 4; l++) {
        int idx = tid + l * 128;                  // 0..511
        int r = idx >> 3, ch = (idx & 7) << 3;
        cp16(sb + OFF_K0 + r * QPITCH + ch * 2, Kg + r * HD + ch);
        cp16(sb + OFF_V0 + r * QPITCH + ch * 2, Vg + r * HD + ch);
    }
    cp_commit();
    #pragma unroll
    for (int l = 0; l < 4; l++) {
        int idx = tid + l * 128;
        int r = idx >> 3, ch = (idx & 7) << 3;
        cp16(sb + OFF_K1 + r * QPITCH + ch * 2, Kg + BN * HD + r * HD + ch);
    }
    cp_commit();
    cp_wait0();
    __syncthreads();

    const int qb = wid * 16;
    const uint32_t abase = ((((lane >> 3) & 1) * 8 + (lane & 7)) * QPITCH) + (((lane >> 4) & 1) * 16);
    const uint32_t kbase = ((((lane >> 4) & 1) * 8 + (lane & 7)) * QPITCH) + (((lane >> 3) & 1) * 16);

    uint32_t Aq[4][4];
    #pragma unroll
    for (int t = 0; t < 4; t++)
        ldsm4(Aq[t], sb + OFF_Q + qb * QPITCH + t * 32 + abase);

    float Oacc[8][4];
    #pragma unroll
    for (int j = 0; j < 8; j++)
        #pragma unroll
        for (int e = 0; e < 4; e++) Oacc[j][e] = 0.0f;

    // ---- issue QK(0) from Kbuf0 ----
    float S[8][4];
    #pragma unroll
    for (int j = 0; j < 8; j++)
        #pragma unroll
        for (int e = 0; e < 4; e++) S[j][e] = 0.0f;
    #pragma unroll
    for (int jp = 0; jp < 4; jp++) {
        #pragma unroll
        for (int t = 0; t < 4; t++) {
            uint32_t B[4];
            ldsm4(B, sb + OFF_K0 + jp * (16 * QPITCH) + t * 32 + kbase);
            mma16816(S[2 * jp],     Aq[t], B);
            mma16816(S[2 * jp + 1], Aq[t], B + 2);
        }
    }
    __syncthreads();   // LDSM(K0) done in all warps before iter-0 prefetch overwrites Kbuf0

    const int row0 = q0 + qb + (lane >> 2);
    const int row1 = row0 + 8;
    const int qv = lane & 3;
    float lsum0 = 0.0f, lsum1 = 0.0f;

    for (int i = 0; i < NKB; i++) {
        // --- prefetch K(i+2) -> kbuf[i&1], V(i+1) -> vbuf[(i+1)&1] ---
        if (i + 2 < NKB) {
            const uint32_t kn = sb + ((i & 1) ? OFF_K1 : OFF_K0);
            const __half* Kn = Kg + (i + 2) * BN * HD;
            #pragma unroll
            for (int l = 0; l < 4; l++) {
                int idx = tid + l * 128;
                int r = idx >> 3, ch = (idx & 7) << 3;
                cp16(kn + r * QPITCH + ch * 2, Kn + r * HD + ch);
            }
            cp_commit();
        }
        if (i + 1 < NKB) {
            const uint32_t vn = sb + (((i + 1) & 1) ? OFF_V1 : OFF_V0);
            const __half* Vn = Vg + (i + 1) * BN * HD;
            #pragma unroll
            for (int l = 0; l < 4; l++) {
                int idx = tid + l * 128;
                int r = idx >> 3, ch = (idx & 7) << 3;
                cp16(vn + r * QPITCH + ch * 2, Vn + r * HD + ch);
            }
            cp_commit();
        }

        uint2 m0 = *reinterpret_cast<const uint2*>(g_mb + row0 * NW + (i << 1));
        uint2 m1 = *reinterpret_cast<const uint2*>(g_mb + row1 * NW + (i << 1));

        // --- softmax(i): e = masked ? 0 : exp2(S) (MUFU pipe) ---
        uint32_t Ap[4][4];
        #pragma unroll
        for (int j = 0; j < 8; j++) {
            unsigned w0 = (j < 4) ? m0.x : m0.y;
            unsigned w1 = (j < 4) ? m1.x : m1.y;
            int p0 = ((j & 3) << 3) + (qv << 1);
            float e0 = ((w0 >> p0) & 1u)       ? 0.0f : ex2(S[j][0]);
            float e1 = ((w0 >> (p0 + 1)) & 1u) ? 0.0f : ex2(S[j][1]);
            float e2 = ((w1 >> p0) & 1u)       ? 0.0f : ex2(S[j][2]);
            float e3 = ((w1 >> (p0 + 1)) & 1u) ? 0.0f : ex2(S[j][3]);
            lsum0 += e0 + e1;
            lsum1 += e2 + e3;
            int t = j >> 1;
            if ((j & 1) == 0) { Ap[t][0] = pack_h2(e0, e1); Ap[t][1] = pack_h2(e2, e3); }
            else              { Ap[t][2] = pack_h2(e0, e1); Ap[t][3] = pack_h2(e2, e3); }
        }

        // --- fused MMA issue: QK(i+1) + PV(i) interleaved ---
        const uint32_t vcur = sb + ((i & 1) ? OFF_V1 : OFF_V0);
        if (i + 1 < NKB) {
            const uint32_t kcur = sb + (((i + 1) & 1) ? OFF_K1 : OFF_K0);
            #pragma unroll
            for (int j = 0; j < 8; j++)
                #pragma unroll
                for (int e = 0; e < 4; e++) S[j][e] = 0.0f;
            #pragma unroll
            for (int jp = 0; jp < 4; jp++) {
                #pragma unroll
                for (int t = 0; t < 4; t++) {
                    uint32_t Bk[4];
                    ldsm4(Bk, kcur + jp * (16 * QPITCH) + t * 32 + kbase);
                    uint32_t Bv[4];
                    ldsm4t(Bv, vcur + t * (16 * QPITCH) + jp * 32 + abase);
                    mma16816(S[2 * jp],        Aq[t], Bk);
                    mma16816(S[2 * jp + 1],    Aq[t], Bk + 2);
                    mma16816(Oacc[2 * jp],     Ap[t], Bv);
                    mma16816(Oacc[2 * jp + 1], Ap[t], Bv + 2);
                }
            }
        } else {
            #pragma unroll
            for (int jp = 0; jp < 4; jp++) {
                #pragma unroll
                for (int t = 0; t < 4; t++) {
                    uint32_t Bv[4];
                    ldsm4t(Bv, vcur + t * (16 * QPITCH) + jp * 32 + abase);
                    mma16816(Oacc[2 * jp],     Ap[t], Bv);
                    mma16816(Oacc[2 * jp + 1], Ap[t], Bv + 2);
                }
            }
        }

        cp_wait0();
        __syncthreads();
    }

    // ---- epilogue ----
    lsum0 += __shfl_xor_sync(0xffffffffu, lsum0, 1);
    lsum0 += __shfl_xor_sync(0xffffffffu, lsum0, 2);
    lsum1 += __shfl_xor_sync(0xffffffffu, lsum1, 1);
    lsum1 += __shfl_xor_sync(0xffffffffu, lsum1, 2);
    float inv0 = 1.0f / lsum0;
    float inv1 = 1.0f / lsum1;

    __half* C0 = g_Ch + h * (SEQ * HD) + row0 * HD;
    __half* C1 = g_Ch + h * (SEQ * HD) + row1 * HD;
    #pragma unroll
    for (int j = 0; j < 8; j++) {
        int c = 8 * j + (qv << 1);
        *reinterpret_cast<uint32_t*>(C0 + c) = pack_h2(Oacc[j][0] * inv0, Oacc[j][1] * inv0);
        *reinterpret_cast<uint32_t*>(C1 + c) = pack_h2(Oacc[j][2] * inv1, Oacc[j][3] * inv1);
    }
}

// ---------------- launch ----------------
extern "C" void kernel_launch(void* const* d_in, const int* in_sizes, int n_in,
                              void* d_out, int out_size)
{
    (void)in_sizes; (void)n_in; (void)out_size;
    const float* x  = (const float*)d_in[0];
    const int*   mk = (const int*)d_in[1];
    const float* wq = (const float*)d_in[2];
    const float* bq = (const float*)d_in[3];
    const float* wk = (const float*)d_in[4];
    const float* bk = (const float*)d_in[5];
    const float* wv = (const float*)d_in[6];
    const float* bv = (const float*)d_in[7];
    const float* dw = (const float*)d_in[8];
    const float* db = (const float*)d_in[9];
    float* out = (float*)d_out;

    cudaFuncSetAttribute(flash_mma_kernel,
                         cudaFuncAttributeMaxDynamicSharedMemorySize, FL_SMEM);

    convert_kernel<<<3072, 256>>>(x, wq, wk, wv, dw);
    hmma_gemm_kernel<false><<<dim3(DMODEL / 128, SEQ / 128, 3), 256>>>(nullptr, nullptr, bq, bk, bv);
    mask_pack_kernel<<<(SEQ * SEQ) / 256, 256>>>(mk);
    flash_mma_kernel<<<dim3(SEQ / BM, NH), 128, FL_SMEM>>>();
    hmma_gemm_kernel<true><<<dim3(DMODEL / 128, SEQ / 128), 256>>>(out, db, nullptr, nullptr, nullptr);
}

// round 11
// speedup vs baseline: 7.0823x; 1.0175x over previous
#include <cuda_runtime.h>
#include <cuda_fp16.h>
#include <cstdint>

#define SEQ    4096
#define DMODEL 512
#define NH     8
#define HD     64
#define KDIM   512
#define NW     (SEQ / 32)   // 128 mask words per row

#define BM 128
#define BN 64
#define NKB (SEQ / BN)

// 0.125 * log2(e): folded into Q projection so flash does exp2(S) directly
#define QSCALE 0.18033688011112042f

// ---------------- scratch (device globals; no allocation allowed) ----------------
__device__ __half   g_Xh[SEQ * KDIM];          // fp16 copy of x
__device__ __half   g_Wh[4 * DMODEL * KDIM];   // wq, wk, wv, dense (fp16)
__device__ __half   g_Qh[SEQ * DMODEL];        // pre-scaled by QSCALE
__device__ __half   g_Kh[SEQ * DMODEL];
__device__ __half   g_Vh[SEQ * DMODEL];
__device__ __half   g_Ch[SEQ * DMODEL];        // context (head-major), fp16
__device__ unsigned g_mb[SEQ * NW];

// ================= helpers =================
__device__ __forceinline__ uint32_t smem_u32(const void* p) {
    uint32_t a;
    asm("{ .reg .u64 t; cvta.to.shared.u64 t, %1; cvt.u32.u64 %0, t; }" : "=r"(a) : "l"(p));
    return a;
}
__device__ __forceinline__ void cp16(uint32_t dst, const void* src) {
    asm volatile("cp.async.cg.shared.global [%0], [%1], 16;" :: "r"(dst), "l"(src));
}
__device__ __forceinline__ void cp_commit() { asm volatile("cp.async.commit_group;"); }
__device__ __forceinline__ void cp_wait0()  { asm volatile("cp.async.wait_group 0;" ::: "memory"); }
__device__ __forceinline__ void cp_wait1()  { asm volatile("cp.async.wait_group 1;" ::: "memory"); }

__device__ __forceinline__ void ldsm4(uint32_t* r, uint32_t addr) {
    asm volatile("ldmatrix.sync.aligned.m8n8.x4.shared.b16 {%0,%1,%2,%3}, [%4];"
        : "=r"(r[0]), "=r"(r[1]), "=r"(r[2]), "=r"(r[3]) : "r"(addr));
}
__device__ __forceinline__ void ldsm4t(uint32_t* r, uint32_t addr) {
    asm volatile("ldmatrix.sync.aligned.m8n8.x4.trans.shared.b16 {%0,%1,%2,%3}, [%4];"
        : "=r"(r[0]), "=r"(r[1]), "=r"(r[2]), "=r"(r[3]) : "r"(addr));
}
// D = A*B + D   (m16n8k16, f16 in, f32 accum)
__device__ __forceinline__ void mma16816(float* d, const uint32_t* a, const uint32_t* b) {
    asm volatile("mma.sync.aligned.m16n8k16.row.col.f32.f16.f16.f32 "
        "{%0,%1,%2,%3}, {%4,%5,%6,%7}, {%8,%9}, {%0,%1,%2,%3};"
        : "+f"(d[0]), "+f"(d[1]), "+f"(d[2]), "+f"(d[3])
        : "r"(a[0]), "r"(a[1]), "r"(a[2]), "r"(a[3]), "r"(b[0]), "r"(b[1]));
}
__device__ __forceinline__ uint32_t pack_h2(float a, float b) {
    __half2 h = __floats2half2_rn(a, b);
    return *reinterpret_cast<uint32_t*>(&h);
}
// 2^x on the MUFU pipe
__device__ __forceinline__ float ex2(float x) {
    float y;
    asm("ex2.approx.ftz.f32 %0, %1;" : "=f"(y) : "f"(x));
    return y;
}

// ---------------- convert: x + 4 weight matrices -> fp16 ----------------
__global__ __launch_bounds__(256) void convert_kernel(
    const float* __restrict__ x,  const float* __restrict__ wq,
    const float* __restrict__ wk, const float* __restrict__ wv,
    const float* __restrict__ dw)
{
    int f4 = blockIdx.x * 256 + threadIdx.x;   // 0 .. 786431
    const float4* src; __half* dst; int off;
    if (f4 < 524288) { src = (const float4*)x; off = f4; dst = g_Xh; }
    else {
        int t = f4 - 524288;
        int w = t >> 16; off = t & 65535;
        src = (const float4*)(w == 0 ? wq : w == 1 ? wk : w == 2 ? wv : dw);
        dst = g_Wh + w * (DMODEL * KDIM);
    }
    float4 v = src[off];
    uint2 u = { pack_h2(v.x, v.y), pack_h2(v.z, v.w) };
    *reinterpret_cast<uint2*>(dst + off * 4) = u;
}

// ---------------- mask pack: int32 [S,S] -> bitmask ----------------
__global__ void mask_pack_kernel(const int* __restrict__ mask)
{
    int gid = blockIdx.x * 256 + threadIdx.x;
    int v = mask[gid];
    unsigned b = __ballot_sync(0xffffffffu, v != 0);
    if ((threadIdx.x & 31) == 0) g_mb[gid >> 5] = b;
}

// ---------------- HMMA GEMM: out = (A @ W^T + bias) * scale ----------------
#define GP 40

template<bool DENSE>
__global__ __launch_bounds__(256) void hmma_gemm_kernel(
    float* __restrict__ outf, const float* __restrict__ dense_b,
    const float* __restrict__ bq, const float* __restrict__ bk,
    const float* __restrict__ bv)
{
    __shared__ __half sA[2][128 * GP];
    __shared__ __half sB[2][128 * GP];

    const int tid = threadIdx.x, lane = tid & 31, wid = tid >> 5;
    const int wm = wid & 1, wn = wid >> 1;
    const int m0 = blockIdx.y * 128, n0 = blockIdx.x * 128;
    const int z = DENSE ? 3 : blockIdx.z;

    const __half* W = g_Wh + z * (DMODEL * KDIM);
    const float* bias = DENSE ? dense_b : (z == 0 ? bq : z == 1 ? bk : bv);
    __half* outh = DENSE ? nullptr : (z == 0 ? g_Qh : z == 1 ? g_Kh : g_Vh);
    const float scale = (!DENSE && z == 0) ? QSCALE : 1.0f;

    const uint32_t sbA = smem_u32(sA), sbB = smem_u32(sB);

    float acc[4][4][4];
    #pragma unroll
    for (int mi = 0; mi < 4; mi++)
        #pragma unroll
        for (int g = 0; g < 4; g++)
            #pragma unroll
            for (int e = 0; e < 4; e++) acc[mi][g][e] = 0.0f;

    const uint32_t abase = ((((lane >> 3) & 1) * 8 + (lane & 7)) * GP) * 2 + ((lane >> 4) & 1) * 16;
    const uint32_t kbase = ((((lane >> 4) & 1) * 8 + (lane & 7)) * GP) * 2 + ((lane >> 3) & 1) * 16;

    #define LOAD_STAGE(kt, buf) do {                                                        \
        const int k0_ = (kt) * 32;                                                          \
        _Pragma("unroll")                                                                   \
        for (int l = 0; l < 2; l++) {                                                       \
            int idx = tid + l * 256;                                                        \
            int r = idx >> 2, c = idx & 3;                                                  \
            const __half* asrc = DENSE                                                      \
                ? (g_Ch + (k0_ >> 6) * (SEQ * HD) + (m0 + r) * HD + (k0_ & 63) + c * 8)     \
                : (g_Xh + (m0 + r) * KDIM + k0_ + c * 8);                                   \
            cp16(sbA + ((buf) * 128 * GP + r * GP) * 2 + c * 16, asrc);                     \
            cp16(sbB + ((buf) * 128 * GP + r * GP) * 2 + c * 16,                            \
                 W + (n0 + r) * KDIM + k0_ + c * 8);                                        \
        }                                                                                   \
        cp_commit();                                                                        \
    } while (0)

    LOAD_STAGE(0, 0);

    for (int kt = 0; kt < KDIM / 32; kt++) {
        const int buf = kt & 1;
        if (kt + 1 < KDIM / 32) { LOAD_STAGE(kt + 1, buf ^ 1); cp_wait1(); }
        else cp_wait0();
        __syncthreads();

        const uint32_t aw = sbA + (buf * 128 * GP + wm * 64 * GP) * 2;
        const uint32_t bw = sbB + (buf * 128 * GP + wn * 32 * GP) * 2;
        #pragma unroll
        for (int t = 0; t < 2; t++) {
            uint32_t Af[4][4];
            #pragma unroll
            for (int mi = 0; mi < 4; mi++)
                ldsm4(Af[mi], aw + (mi * 16 * GP) * 2 + t * 32 + abase);
            uint32_t Bf[2][4];
            #pragma unroll
            for (int bi = 0; bi < 2; bi++)
                ldsm4(Bf[bi], bw + (bi * 16 * GP) * 2 + t * 32 + kbase);
            #pragma unroll
            for (int mi = 0; mi < 4; mi++)
                #pragma unroll
                for (int bi = 0; bi < 2; bi++) {
                    mma16816(acc[mi][bi * 2],     Af[mi], Bf[bi]);
                    mma16816(acc[mi][bi * 2 + 1], Af[mi], Bf[bi] + 2);
                }
        }
        __syncthreads();
    }
    #undef LOAD_STAGE

    const int qr = lane >> 2, qc = (lane & 3) << 1;
    #pragma unroll
    for (int mi = 0; mi < 4; mi++) {
        int mrow = m0 + wm * 64 + mi * 16 + qr;
        #pragma unroll
        for (int g = 0; g < 4; g++) {
            int n = n0 + wn * 32 + g * 8 + qc;
            float b0 = bias[n], b1 = bias[n + 1];
            if (DENSE) {
                float2 u0 = { acc[mi][g][0] + b0, acc[mi][g][1] + b1 };
                float2 u1 = { acc[mi][g][2] + b0, acc[mi][g][3] + b1 };
                *reinterpret_cast<float2*>(outf + mrow * DMODEL + n)       = u0;
                *reinterpret_cast<float2*>(outf + (mrow + 8) * DMODEL + n) = u1;
            } else {
                uint32_t u0 = pack_h2((acc[mi][g][0] + b0) * scale, (acc[mi][g][1] + b1) * scale);
                uint32_t u1 = pack_h2((acc[mi][g][2] + b0) * scale, (acc[mi][g][3] + b1) * scale);
                *reinterpret_cast<uint32_t*>(outh + mrow * DMODEL + n)       = u0;
                *reinterpret_cast<uint32_t*>(outh + (mrow + 8) * DMODEL + n) = u1;
            }
        }
    }
}

// ---------------- fp16 mma.sync flash attention (pipelined, 32 q-rows/warp) ----------------
// BM=128, 128 threads (4 warps x 32 q-rows = 2 row-tiles each), 2 CTAs/SM.
// Each B-fragment (K or V) loaded once per warp feeds BOTH row-tiles (8 MMAs)
// -> halves ldmatrix smem traffic per flop vs 16-row warps.
#define QPITCH 144
#define OFF_Q   0
#define OFF_K0  (128 * QPITCH)
#define OFF_K1  (OFF_K0 + 64 * QPITCH)
#define OFF_V0  (OFF_K1 + 64 * QPITCH)
#define OFF_V1  (OFF_V0 + 64 * QPITCH)
#define FL_SMEM (OFF_V1 + 64 * QPITCH)         // (128+4*64)*144 = 55296 B

__global__ void __launch_bounds__(128, 2) flash_mma_kernel()
{
    extern __shared__ __align__(128) char smem[];
    const uint32_t sb = smem_u32(smem);
    const int tid  = threadIdx.x;
    const int wid  = tid >> 5;
    const int lane = tid & 31;
    const int h    = blockIdx.y;
    const int q0   = blockIdx.x * BM;
    const __half* Qg = g_Qh + h * (SEQ * HD);
    const __half* Kg = g_Kh + h * (SEQ * HD);
    const __half* Vg = g_Vh + h * (SEQ * HD);

    // ---- prologue: Q -> smem (padded); K0,V0 (group), K1 (group) ----
    {
        int r = tid;                              // 128 rows, one per thread
        const uint4* src = reinterpret_cast<const uint4*>(Qg + (q0 + r) * HD);
        char* dst = smem + OFF_Q + r * QPITCH;
        #pragma unroll
        for (int k = 0; k < 8; k++)
            reinterpret_cast<uint4*>(dst)[k] = src[k];
    }
    #pragma unroll
    for (int l = 0; l < 4; l++) {
        int idx = tid + l * 128;                  // 0..511
        int r = idx >> 3, ch = (idx & 7) << 3;
        cp16(sb + OFF_K0 + r * QPITCH + ch * 2, Kg + r * HD + ch);
        cp16(sb + OFF_V0 + r * QPITCH + ch * 2, Vg + r * HD + ch);
    }
    cp_commit();
    #pragma unroll
    for (int l = 0; l < 4; l++) {
        int idx = tid + l * 128;
        int r = idx >> 3, ch = (idx & 7) << 3;
        cp16(sb + OFF_K1 + r * QPITCH + ch * 2, Kg + BN * HD + r * HD + ch);
    }
    cp_commit();
    cp_wait0();
    __syncthreads();

    const int qb = wid * 32;
    const uint32_t abase = ((((lane >> 3) & 1) * 8 + (lane & 7)) * QPITCH) + (((lane >> 4) & 1) * 16);
    const uint32_t kbase = ((((lane >> 4) & 1) * 8 + (lane & 7)) * QPITCH) + (((lane >> 3) & 1) * 16);

    uint32_t Aq[2][4][4];
    #pragma unroll
    for (int u = 0; u < 2; u++)
        #pragma unroll
        for (int t = 0; t < 4; t++)
            ldsm4(Aq[u][t], sb + OFF_Q + (qb + u * 16) * QPITCH + t * 32 + abase);

    float Oacc[2][8][4];
    #pragma unroll
    for (int u = 0; u < 2; u++)
        #pragma unroll
        for (int j = 0; j < 8; j++)
            #pragma unroll
            for (int e = 0; e < 4; e++) Oacc[u][j][e] = 0.0f;

    // ---- issue QK(0) from Kbuf0 (B-frag shared across both row-tiles) ----
    float S[2][8][4];
    #pragma unroll
    for (int u = 0; u < 2; u++)
        #pragma unroll
        for (int j = 0; j < 8; j++)
            #pragma unroll
            for (int e = 0; e < 4; e++) S[u][j][e] = 0.0f;
    #pragma unroll
    for (int jp = 0; jp < 4; jp++) {
        #pragma unroll
        for (int t = 0; t < 4; t++) {
            uint32_t B[4];
            ldsm4(B, sb + OFF_K0 + jp * (16 * QPITCH) + t * 32 + kbase);
            #pragma unroll
            for (int u = 0; u < 2; u++) {
                mma16816(S[u][2 * jp],     Aq[u][t], B);
                mma16816(S[u][2 * jp + 1], Aq[u][t], B + 2);
            }
        }
    }
    __syncthreads();   // LDSM(K0) done in all warps before iter-0 prefetch overwrites Kbuf0

    const int rowb = q0 + qb + (lane >> 2);
    const int qv = lane & 3;
    float lsum[2][2] = { {0.0f, 0.0f}, {0.0f, 0.0f} };

    for (int i = 0; i < NKB; i++) {
        // --- prefetch K(i+2) -> kbuf[i&1], V(i+1) -> vbuf[(i+1)&1] ---
        if (i + 2 < NKB) {
            const uint32_t kn = sb + ((i & 1) ? OFF_K1 : OFF_K0);
            const __half* Kn = Kg + (i + 2) * BN * HD;
            #pragma unroll
            for (int l = 0; l < 4; l++) {
                int idx = tid + l * 128;
                int r = idx >> 3, ch = (idx & 7) << 3;
                cp16(kn + r * QPITCH + ch * 2, Kn + r * HD + ch);
            }
            cp_commit();
        }
        if (i + 1 < NKB) {
            const uint32_t vn = sb + (((i + 1) & 1) ? OFF_V1 : OFF_V0);
            const __half* Vn = Vg + (i + 1) * BN * HD;
            #pragma unroll
            for (int l = 0; l < 4; l++) {
                int idx = tid + l * 128;
                int r = idx >> 3, ch = (idx & 7) << 3;
                cp16(vn + r * QPITCH + ch * 2, Vn + r * HD + ch);
            }
            cp_commit();
        }

        // --- softmax(i) per row-tile: e = masked ? 0 : exp2(S) (MUFU pipe) ---
        uint32_t Ap[2][4][4];
        #pragma unroll
        for (int u = 0; u < 2; u++) {
            uint2 m0 = *reinterpret_cast<const uint2*>(g_mb + (rowb + u * 16)     * NW + (i << 1));
            uint2 m1 = *reinterpret_cast<const uint2*>(g_mb + (rowb + u * 16 + 8) * NW + (i << 1));
            #pragma unroll
            for (int j = 0; j < 8; j++) {
                unsigned w0 = (j < 4) ? m0.x : m0.y;
                unsigned w1 = (j < 4) ? m1.x : m1.y;
                int p0 = ((j & 3) << 3) + (qv << 1);
                float e0 = ((w0 >> p0) & 1u)       ? 0.0f : ex2(S[u][j][0]);
                float e1 = ((w0 >> (p0 + 1)) & 1u) ? 0.0f : ex2(S[u][j][1]);
                float e2 = ((w1 >> p0) & 1u)       ? 0.0f : ex2(S[u][j][2]);
                float e3 = ((w1 >> (p0 + 1)) & 1u) ? 0.0f : ex2(S[u][j][3]);
                lsum[u][0] += e0 + e1;
                lsum[u][1] += e2 + e3;
                int t = j >> 1;
                if ((j & 1) == 0) { Ap[u][t][0] = pack_h2(e0, e1); Ap[u][t][1] = pack_h2(e2, e3); }
                else              { Ap[u][t][2] = pack_h2(e0, e1); Ap[u][t][3] = pack_h2(e2, e3); }
            }
        }

        // --- fused MMA issue: QK(i+1) + PV(i), B-frags reused across row-tiles ---
        const uint32_t vcur = sb + ((i & 1) ? OFF_V1 : OFF_V0);
        if (i + 1 < NKB) {
            const uint32_t kcur = sb + (((i + 1) & 1) ? OFF_K1 : OFF_K0);
            #pragma unroll
            for (int u = 0; u < 2; u++)
                #pragma unroll
                for (int j = 0; j < 8; j++)
                    #pragma unroll
                    for (int e = 0; e < 4; e++) S[u][j][e] = 0.0f;
            #pragma unroll
            for (int jp = 0; jp < 4; jp++) {
                #pragma unroll
                for (int t = 0; t < 4; t++) {
                    uint32_t Bk[4];
                    ldsm4(Bk, kcur + jp * (16 * QPITCH) + t * 32 + kbase);
                    uint32_t Bv[4];
                    ldsm4t(Bv, vcur + t * (16 * QPITCH) + jp * 32 + abase);
                    #pragma unroll
                    for (int u = 0; u < 2; u++) {
                        mma16816(S[u][2 * jp],        Aq[u][t], Bk);
                        mma16816(S[u][2 * jp + 1],    Aq[u][t], Bk + 2);
                        mma16816(Oacc[u][2 * jp],     Ap[u][t], Bv);
                        mma16816(Oacc[u][2 * jp + 1], Ap[u][t], Bv + 2);
                    }
                }
            }
        } else {
            #pragma unroll
            for (int jp = 0; jp < 4; jp++) {
                #pragma unroll
                for (int t = 0; t < 4; t++) {
                    uint32_t Bv[4];
                    ldsm4t(Bv, vcur + t * (16 * QPITCH) + jp * 32 + abase);
                    #pragma unroll
                    for (int u = 0; u < 2; u++) {
                        mma16816(Oacc[u][2 * jp],     Ap[u][t], Bv);
                        mma16816(Oacc[u][2 * jp + 1], Ap[u][t], Bv + 2);
                    }
                }
            }
        }

        cp_wait0();
        __syncthreads();
    }

    // ---- epilogue ----
    #pragma unroll
    for (int u = 0; u < 2; u++) {
        float l0 = lsum[u][0], l1 = lsum[u][1];
        l0 += __shfl_xor_sync(0xffffffffu, l0, 1);
        l0 += __shfl_xor_sync(0xffffffffu, l0, 2);
        l1 += __shfl_xor_sync(0xffffffffu, l1, 1);
        l1 += __shfl_xor_sync(0xffffffffu, l1, 2);
        float inv0 = 1.0f / l0;
        float inv1 = 1.0f / l1;

        __half* C0 = g_Ch + h * (SEQ * HD) + (rowb + u * 16) * HD;
        __half* C1 = C0 + 8 * HD;
        #pragma unroll
        for (int j = 0; j < 8; j++) {
            int c = 8 * j + (qv << 1);
            *reinterpret_cast<uint32_t*>(C0 + c) = pack_h2(Oacc[u][j][0] * inv0, Oacc[u][j][1] * inv0);
            *reinterpret_cast<uint32_t*>(C1 + c) = pack_h2(Oacc[u][j][2] * inv1, Oacc[u][j][3] * inv1);
        }
    }
}

// ---------------- launch ----------------
extern "C" void kernel_launch(void* const* d_in, const int* in_sizes, int n_in,
                              void* d_out, int out_size)
{
    (void)in_sizes; (void)n_in; (void)out_size;
    const float* x  = (const float*)d_in[0];
    const int*   mk = (const int*)d_in[1];
    const float* wq = (const float*)d_in[2];
    const float* bq = (const float*)d_in[3];
    const float* wk = (const float*)d_in[4];
    const float* bk = (const float*)d_in[5];
    const float* wv = (const float*)d_in[6];
    const float* bv = (const float*)d_in[7];
    const float* dw = (const float*)d_in[8];
    const float* db = (const float*)d_in[9];
    float* out = (float*)d_out;

    cudaFuncSetAttribute(flash_mma_kernel,
                         cudaFuncAttributeMaxDynamicSharedMemorySize, FL_SMEM);

    convert_kernel<<<3072, 256>>>(x, wq, wk, wv, dw);
    hmma_gemm_kernel<false><<<dim3(DMODEL / 128, SEQ / 128, 3), 256>>>(nullptr, nullptr, bq, bk, bv);
    mask_pack_kernel<<<(SEQ * SEQ) / 256, 256>>>(mk);
    flash_mma_kernel<<<dim3(SEQ / BM, NH), 128, FL_SMEM>>>();
    hmma_gemm_kernel<true><<<dim3(DMODEL / 128, SEQ / 128), 256>>>(out, db, nullptr, nullptr, nullptr);
}